// round 1
// baseline (speedup 1.0000x reference)
#include <cuda_runtime.h>
#include <math.h>

// Problem constants (B=1, D=H=W=28, C=384, NH=12, WS=7)
#define LTOT  21952          // 28^3 tokens
#define CH    384
#define NWIN  64             // 4*4*4 windows
#define NTOK  343            // 7^3 tokens per window
#define NHEAD 12
#define HD    32             // head dim
#define KPAD  345            // padded K-transpose stride (gcd(345,32)=1)

// ---------------- scratch (device globals; no allocations allowed) ----------
__device__ float g_ln_skip[LTOT * CH];    // LN(skip), window-row layout
__device__ float g_ln_q[LTOT * CH];       // LN(x_up)*hd^-0.5, window-row layout
__device__ float g_kv[LTOT * 2 * CH];     // kv proj, window-row layout
__device__ float g_o[LTOT * CH];          // attention out, window-row layout
__device__ float g_x[LTOT * CH];          // x_up+skip+proj_out, spatial layout
__device__ float g_ln2[LTOT * CH];        // LN2(x), spatial layout
__device__ float g_h1[LTOT * 4 * CH];     // gelu(mlp1), spatial layout

// spatial token l -> window row r
__device__ __forceinline__ int l_to_winrow(int l) {
    int d = l / 784, rem = l % 784, h = rem / 28, w = rem % 28;
    int win = (d / 7) * 16 + (h / 7) * 4 + (w / 7);
    int p = (d % 7) * 49 + (h % 7) * 7 + (w % 7);
    return win * NTOK + p;
}
// window row r -> spatial token l
__device__ __forceinline__ int winrow_to_l(int r) {
    int win = r / NTOK, p = r % NTOK;
    int wd = win >> 4, wh = (win >> 2) & 3, ww = win & 3;
    int pd = p / 49, ph = (p / 7) % 7, pw = p % 7;
    return (wd * 7 + pd) * 784 + (wh * 7 + ph) * 28 + (ww * 7 + pw);
}

// ---------------- LN1: dual layernorm + window partition ----------------
__global__ void ln1_kernel(const float* __restrict__ skip, const float* __restrict__ xup,
                           const float* __restrict__ g, const float* __restrict__ b) {
    int l = blockIdx.x;
    int tid = threadIdx.x;
    __shared__ float red[16];
    const float* sp = skip + (size_t)l * CH;
    const float* xp = xup + (size_t)l * CH;
    float v1[3], v2[3];
    float s1 = 0.f, q1 = 0.f, s2 = 0.f, q2 = 0.f;
#pragma unroll
    for (int i = 0; i < 3; i++) {
        int c = tid + i * 128;
        v1[i] = sp[c]; v2[i] = xp[c];
        s1 += v1[i]; q1 += v1[i] * v1[i];
        s2 += v2[i]; q2 += v2[i] * v2[i];
    }
#pragma unroll
    for (int o = 16; o > 0; o >>= 1) {
        s1 += __shfl_xor_sync(0xffffffffu, s1, o);
        q1 += __shfl_xor_sync(0xffffffffu, q1, o);
        s2 += __shfl_xor_sync(0xffffffffu, s2, o);
        q2 += __shfl_xor_sync(0xffffffffu, q2, o);
    }
    int wid = tid >> 5;
    if ((tid & 31) == 0) { red[wid] = s1; red[wid + 4] = q1; red[wid + 8] = s2; red[wid + 12] = q2; }
    __syncthreads();
    s1 = red[0] + red[1] + red[2] + red[3];
    q1 = red[4] + red[5] + red[6] + red[7];
    s2 = red[8] + red[9] + red[10] + red[11];
    q2 = red[12] + red[13] + red[14] + red[15];
    const float invC = 1.0f / CH;
    float m1 = s1 * invC, m2 = s2 * invC;
    float r1 = rsqrtf(q1 * invC - m1 * m1 + 1e-5f);
    float r2 = rsqrtf(q2 * invC - m2 * m2 + 1e-5f);
    int r = l_to_winrow(l);
    float* o1 = g_ln_skip + (size_t)r * CH;
    float* o2 = g_ln_q + (size_t)r * CH;
    const float QS = 0.17677669529663687f;  // hd^-0.5
#pragma unroll
    for (int i = 0; i < 3; i++) {
        int c = tid + i * 128;
        float gg = g[c], bb = b[c];
        o1[c] = (v1[i] - m1) * r1 * gg + bb;
        o2[c] = ((v2[i] - m2) * r2 * gg + bb) * QS;
    }
}

// ---------------- LN2: single layernorm on g_x (spatial) ----------------
__global__ void ln2_kernel(const float* __restrict__ g, const float* __restrict__ b) {
    int l = blockIdx.x;
    int tid = threadIdx.x;
    __shared__ float red[8];
    const float* xp = g_x + (size_t)l * CH;
    float v[3];
    float s = 0.f, q = 0.f;
#pragma unroll
    for (int i = 0; i < 3; i++) {
        v[i] = xp[tid + i * 128];
        s += v[i]; q += v[i] * v[i];
    }
#pragma unroll
    for (int o = 16; o > 0; o >>= 1) {
        s += __shfl_xor_sync(0xffffffffu, s, o);
        q += __shfl_xor_sync(0xffffffffu, q, o);
    }
    int wid = tid >> 5;
    if ((tid & 31) == 0) { red[wid] = s; red[wid + 4] = q; }
    __syncthreads();
    s = red[0] + red[1] + red[2] + red[3];
    q = red[4] + red[5] + red[6] + red[7];
    const float invC = 1.0f / CH;
    float m = s * invC;
    float rs = rsqrtf(q * invC - m * m + 1e-5f);
    float* op = g_ln2 + (size_t)l * CH;
#pragma unroll
    for (int i = 0; i < 3; i++) {
        int c = tid + i * 128;
        op[c] = (v[i] - m) * rs * g[c] + b[c];
    }
}

// ---------------- tiled SGEMM 128x128x8 with fused epilogues ----------------
// EPI 0: kv    (A=g_ln_skip)  out = acc + kv_b          -> g_kv
// EPI 1: proj  (A=g_o)        g_x[l] = skip[l]+xup[l]+acc+pb  (winrow->l map)
// EPI 2: mlp1  (A=g_ln2)      g_h1 = gelu_tanh(acc+b1)
// EPI 3: mlp2  (A=g_h1)       out[l] = g_x[l]+acc+b2    -> d_out
template <int EPI>
__global__ void gemm_kernel(const float* __restrict__ B, const float* __restrict__ bias,
                            const float* __restrict__ e1, const float* __restrict__ e2,
                            float* __restrict__ out, int M, int N, int K) {
    const float* A = (EPI == 0) ? g_ln_skip : (EPI == 1) ? g_o : (EPI == 2) ? g_ln2 : g_h1;
    __shared__ __align__(16) float As[8][128];
    __shared__ __align__(16) float Bs[8][128];
    int tid = threadIdx.x;
    int bm = blockIdx.y, bn = blockIdx.x;
    int aRow = tid >> 1, aCol = (tid & 1) * 4;
    int bRow = tid >> 5, bCol = (tid & 31) * 4;
    int ty = tid >> 4, tx = tid & 15;
    float acc[8][8] = {};
    int rowBase = bm * 128;
    bool aValid = (rowBase + aRow) < M;
    const float* Aptr = A + (size_t)(rowBase + aRow) * K + aCol;
    const float* Bptr = B + (size_t)bRow * N + bn * 128 + bCol;
    for (int k0 = 0; k0 < K; k0 += 8) {
        float4 av = aValid ? *(const float4*)(Aptr + k0) : make_float4(0.f, 0.f, 0.f, 0.f);
        float4 bv = *(const float4*)(Bptr + (size_t)k0 * N);
        As[aCol + 0][aRow] = av.x; As[aCol + 1][aRow] = av.y;
        As[aCol + 2][aRow] = av.z; As[aCol + 3][aRow] = av.w;
        *(float4*)&Bs[bRow][bCol] = bv;
        __syncthreads();
#pragma unroll
        for (int kk = 0; kk < 8; kk++) {
            float ra[8], rb[8];
#pragma unroll
            for (int i = 0; i < 8; i++) ra[i] = As[kk][ty * 8 + i];
#pragma unroll
            for (int j = 0; j < 8; j++) rb[j] = Bs[kk][tx * 8 + j];
#pragma unroll
            for (int i = 0; i < 8; i++)
#pragma unroll
                for (int j = 0; j < 8; j++)
                    acc[i][j] += ra[i] * rb[j];
        }
        __syncthreads();
    }
#pragma unroll
    for (int i = 0; i < 8; i++) {
        int row = rowBase + ty * 8 + i;
        if (row >= M) break;
        int l = 0;
        if (EPI == 1) l = winrow_to_l(row);
#pragma unroll
        for (int j = 0; j < 8; j++) {
            int col = bn * 128 + tx * 8 + j;
            float v = acc[i][j] + bias[col];
            if (EPI == 0) {
                g_kv[(size_t)row * 768 + col] = v;
            } else if (EPI == 1) {
                size_t idx = (size_t)l * CH + col;
                g_x[idx] = e1[idx] + e2[idx] + v;
            } else if (EPI == 2) {
                float t = tanhf(0.7978845608028654f * (v + 0.044715f * v * v * v));
                g_h1[(size_t)row * 1536 + col] = 0.5f * v * (1.0f + t);
            } else {
                size_t idx = (size_t)row * CH + col;
                out[idx] = g_x[idx] + v;
            }
        }
    }
}

// ---------------- fused window attention (one block per window x head) ------
// smem: q[343*32] + kT[32*345] + v[343*32] + bias[2197] + p[8*343] = ~151.7 KB
#define ATTN_SMEM ((NTOK * HD * 2 + HD * KPAD + 2197 + 8 * NTOK) * 4)

__global__ void attn_kernel(const float* __restrict__ rpb) {
    int win = blockIdx.x, head = blockIdx.y;
    extern __shared__ float sm[];
    float* q_s = sm;                    // [343][32]
    float* k_s = q_s + NTOK * HD;       // [32][345] transposed
    float* v_s = k_s + HD * KPAD;       // [343][32]
    float* bias_s = v_s + NTOK * HD;    // [2197]
    float* p_s = bias_s + 2197;         // [8][343]
    int tid = threadIdx.x;
    const size_t base = (size_t)win * NTOK;
    for (int idx = tid; idx < NTOK * HD; idx += 256) {
        int j = idx >> 5, d = idx & 31;
        q_s[idx] = g_ln_q[(base + j) * CH + head * HD + d];
        k_s[d * KPAD + j] = g_kv[(base + j) * 768 + head * HD + d];
        v_s[idx] = g_kv[(base + j) * 768 + 384 + head * HD + d];
    }
    for (int idx = tid; idx < 2197; idx += 256)
        bias_s[idx] = rpb[idx * NHEAD + head];
    __syncthreads();

    int lane = tid & 31, wid = tid >> 5;
    float* pw = p_s + wid * NTOK;
    for (int r = wid; r < NTOK; r += 8) {
        float qv[32];
#pragma unroll
        for (int d = 0; d < 32; d++) qv[d] = q_s[r * 32 + d];
        int pd = r / 49, ph = (r / 7) % 7, pwc = r % 7;
        float sv[11];
        float smax = -1e30f;
#pragma unroll
        for (int t = 0; t < 11; t++) {
            int j = lane + t * 32;
            if (j < NTOK) {
                int kd = j / 49, kh = (j / 7) % 7, kw = j % 7;
                float s = bias_s[(pd - kd + 6) * 169 + (ph - kh + 6) * 13 + (pwc - kw + 6)];
#pragma unroll
                for (int d = 0; d < 32; d++) s += qv[d] * k_s[d * KPAD + j];
                sv[t] = s;
                smax = fmaxf(smax, s);
            } else {
                sv[t] = -1e30f;
            }
        }
#pragma unroll
        for (int o = 16; o > 0; o >>= 1)
            smax = fmaxf(smax, __shfl_xor_sync(0xffffffffu, smax, o));
        __syncwarp();
        float ssum = 0.f;
#pragma unroll
        for (int t = 0; t < 11; t++) {
            int j = lane + t * 32;
            if (j < NTOK) {
                float e = __expf(sv[t] - smax);
                ssum += e;
                pw[j] = e;
            }
        }
#pragma unroll
        for (int o = 16; o > 0; o >>= 1)
            ssum += __shfl_xor_sync(0xffffffffu, ssum, o);
        float inv = 1.0f / ssum;
        __syncwarp();
        float acc = 0.f;
#pragma unroll 7
        for (int j = 0; j < NTOK; j++)
            acc += pw[j] * v_s[j * 32 + lane];
        g_o[(base + r) * CH + head * HD + lane] = acc * inv;
        __syncwarp();
    }
}

// ---------------- launch ----------------
extern "C" void kernel_launch(void* const* d_in, const int* in_sizes, int n_in,
                              void* d_out, int out_size) {
    const float* skip = (const float*)d_in[0];
    const float* xup  = (const float*)d_in[1];
    const float* ln1g = (const float*)d_in[5];
    const float* ln1b = (const float*)d_in[6];
    const float* kvw  = (const float*)d_in[7];
    const float* kvb  = (const float*)d_in[8];
    const float* rpb  = (const float*)d_in[9];
    const float* pw   = (const float*)d_in[10];
    const float* pb   = (const float*)d_in[11];
    const float* ln2g = (const float*)d_in[12];
    const float* ln2b = (const float*)d_in[13];
    const float* w1   = (const float*)d_in[14];
    const float* b1   = (const float*)d_in[15];
    const float* w2   = (const float*)d_in[16];
    const float* b2   = (const float*)d_in[17];
    float* out = (float*)d_out;

    cudaFuncSetAttribute(attn_kernel, cudaFuncAttributeMaxDynamicSharedMemorySize, ATTN_SMEM);

    ln1_kernel<<<LTOT, 128>>>(skip, xup, ln1g, ln1b);
    gemm_kernel<0><<<dim3(6, 172), 256>>>(kvw, kvb, nullptr, nullptr, nullptr, LTOT, 768, 384);
    attn_kernel<<<dim3(NWIN, NHEAD), 256, ATTN_SMEM>>>(rpb);
    gemm_kernel<1><<<dim3(3, 172), 256>>>(pw, pb, skip, xup, nullptr, LTOT, 384, 384);
    ln2_kernel<<<LTOT, 128>>>(ln2g, ln2b);
    gemm_kernel<2><<<dim3(12, 172), 256>>>(w1, b1, nullptr, nullptr, nullptr, LTOT, 1536, 384);
    gemm_kernel<3><<<dim3(3, 172), 256>>>(w2, b2, nullptr, nullptr, out, LTOT, 384, 1536);
}

// round 8
// speedup vs baseline: 1.6120x; 1.6120x over previous
#include <cuda_runtime.h>
#include <cuda_bf16.h>
#include <cstdint>
#include <math.h>

// Problem constants (B=1, D=H=W=28, C=384, NH=12, WS=7)
#define LTOT  21952
#define CH    384
#define NWIN  64
#define NTOK  343
#define NHEAD 12
#define HD    32
#define KPAD  345

// ---------------- scratch ----------------
__device__ float g_ln_q[LTOT * CH];
__device__ __nv_bfloat16 g_lnskip_h[LTOT * CH], g_lnskip_l[LTOT * CH];
__device__ float g_kv[LTOT * 2 * CH];
__device__ __nv_bfloat16 g_oh[LTOT * CH], g_ol[LTOT * CH];
__device__ float g_x[LTOT * CH];
__device__ __nv_bfloat16 g_ln2h[LTOT * CH], g_ln2l[LTOT * CH];
__device__ __nv_bfloat16 g_h1h[LTOT * 4 * CH], g_h1l[LTOT * 4 * CH];
__device__ __nv_bfloat16 g_wkv_h[768 * 384], g_wkv_l[768 * 384];
__device__ __nv_bfloat16 g_wp_h[384 * 384], g_wp_l[384 * 384];
__device__ __nv_bfloat16 g_w1_h[1536 * 384], g_w1_l[1536 * 384];
__device__ __nv_bfloat16 g_w2_h[384 * 1536], g_w2_l[384 * 1536];

__device__ __forceinline__ int l_to_winrow(int l) {
    int d = l / 784, rem = l % 784, h = rem / 28, w = rem % 28;
    int win = (d / 7) * 16 + (h / 7) * 4 + (w / 7);
    int p = (d % 7) * 49 + (h % 7) * 7 + (w % 7);
    return win * NTOK + p;
}
__device__ __forceinline__ int winrow_to_l(int r) {
    int win = r / NTOK, p = r % NTOK;
    int wd = win >> 4, wh = (win >> 2) & 3, ww = win & 3;
    int pd = p / 49, ph = (p / 7) % 7, pw = p % 7;
    return (wd * 7 + pd) * 784 + (wh * 7 + ph) * 28 + (ww * 7 + pw);
}
__device__ __forceinline__ void split_bf16(float v, __nv_bfloat16* h, __nv_bfloat16* l) {
    __nv_bfloat16 hh = __float2bfloat16(v);
    *h = hh;
    *l = __float2bfloat16(v - __bfloat162float(hh));
}

// ---------------- mma.sync helpers ----------------
__device__ __forceinline__ uint32_t smem_u32(const void* p) {
    uint32_t a;
    asm("{ .reg .u64 t; cvta.to.shared.u64 t, %1; cvt.u32.u64 %0, t; }" : "=r"(a) : "l"(p));
    return a;
}
__device__ __forceinline__ void ldsm_x4(uint32_t* r, uint32_t addr) {
    asm volatile("ldmatrix.sync.aligned.m8n8.x4.shared.b16 {%0,%1,%2,%3}, [%4];"
                 : "=r"(r[0]), "=r"(r[1]), "=r"(r[2]), "=r"(r[3]) : "r"(addr));
}
__device__ __forceinline__ void ldsm_x2(uint32_t* r, uint32_t addr) {
    asm volatile("ldmatrix.sync.aligned.m8n8.x2.shared.b16 {%0,%1}, [%2];"
                 : "=r"(r[0]), "=r"(r[1]) : "r"(addr));
}
__device__ __forceinline__ void mma_bf16(float* d, const uint32_t* a, const uint32_t* b) {
    asm volatile(
        "mma.sync.aligned.m16n8k16.row.col.f32.bf16.bf16.f32 "
        "{%0,%1,%2,%3}, {%4,%5,%6,%7}, {%8,%9}, {%0,%1,%2,%3};"
        : "+f"(d[0]), "+f"(d[1]), "+f"(d[2]), "+f"(d[3])
        : "r"(a[0]), "r"(a[1]), "r"(a[2]), "r"(a[3]), "r"(b[0]), "r"(b[1]));
}

// ---------------- weight transpose + hi/lo convert: Th[n][k] = W[k][n] ------
template <int WID>
__global__ void wconv(const float* __restrict__ W, int K, int N) {
    __nv_bfloat16* Th = (WID == 0) ? g_wkv_h : (WID == 1) ? g_wp_h : (WID == 2) ? g_w1_h : g_w2_h;
    __nv_bfloat16* Tl = (WID == 0) ? g_wkv_l : (WID == 1) ? g_wp_l : (WID == 2) ? g_w1_l : g_w2_l;
    __shared__ float t[32][33];
    int nb = blockIdx.x * 32, kb = blockIdx.y * 32;
    int tx = threadIdx.x, ty = threadIdx.y;
#pragma unroll
    for (int i = 0; i < 4; i++) {
        int k = ty + i * 8;
        t[k][tx] = W[(size_t)(kb + k) * N + nb + tx];
    }
    __syncthreads();
#pragma unroll
    for (int i = 0; i < 4; i++) {
        int nrow = ty + i * 8;
        float v = t[tx][nrow];
        size_t o = (size_t)(nb + nrow) * K + kb + tx;
        split_bf16(v, &Th[o], &Tl[o]);
    }
}

// ---------------- LN1 ----------------
__global__ void ln1_kernel(const float* __restrict__ skip, const float* __restrict__ xup,
                           const float* __restrict__ g, const float* __restrict__ b) {
    int l = blockIdx.x;
    int tid = threadIdx.x;
    __shared__ float red[16];
    const float* sp = skip + (size_t)l * CH;
    const float* xp = xup + (size_t)l * CH;
    float v1[3], v2[3];
    float s1 = 0.f, q1 = 0.f, s2 = 0.f, q2 = 0.f;
#pragma unroll
    for (int i = 0; i < 3; i++) {
        int c = tid + i * 128;
        v1[i] = sp[c]; v2[i] = xp[c];
        s1 += v1[i]; q1 += v1[i] * v1[i];
        s2 += v2[i]; q2 += v2[i] * v2[i];
    }
#pragma unroll
    for (int o = 16; o > 0; o >>= 1) {
        s1 += __shfl_xor_sync(0xffffffffu, s1, o);
        q1 += __shfl_xor_sync(0xffffffffu, q1, o);
        s2 += __shfl_xor_sync(0xffffffffu, s2, o);
        q2 += __shfl_xor_sync(0xffffffffu, q2, o);
    }
    int wid = tid >> 5;
    if ((tid & 31) == 0) { red[wid] = s1; red[wid + 4] = q1; red[wid + 8] = s2; red[wid + 12] = q2; }
    __syncthreads();
    s1 = red[0] + red[1] + red[2] + red[3];
    q1 = red[4] + red[5] + red[6] + red[7];
    s2 = red[8] + red[9] + red[10] + red[11];
    q2 = red[12] + red[13] + red[14] + red[15];
    const float invC = 1.0f / CH;
    float m1 = s1 * invC, m2 = s2 * invC;
    float r1 = rsqrtf(q1 * invC - m1 * m1 + 1e-5f);
    float r2 = rsqrtf(q2 * invC - m2 * m2 + 1e-5f);
    int r = l_to_winrow(l);
    const float QS = 0.17677669529663687f;
#pragma unroll
    for (int i = 0; i < 3; i++) {
        int c = tid + i * 128;
        float gg = g[c], bb = b[c];
        float o1 = (v1[i] - m1) * r1 * gg + bb;
        size_t idx = (size_t)r * CH + c;
        split_bf16(o1, &g_lnskip_h[idx], &g_lnskip_l[idx]);
        g_ln_q[idx] = ((v2[i] - m2) * r2 * gg + bb) * QS;
    }
}

// ---------------- LN2 ----------------
__global__ void ln2_kernel(const float* __restrict__ g, const float* __restrict__ b) {
    int l = blockIdx.x;
    int tid = threadIdx.x;
    __shared__ float red[8];
    const float* xp = g_x + (size_t)l * CH;
    float v[3];
    float s = 0.f, q = 0.f;
#pragma unroll
    for (int i = 0; i < 3; i++) {
        v[i] = xp[tid + i * 128];
        s += v[i]; q += v[i] * v[i];
    }
#pragma unroll
    for (int o = 16; o > 0; o >>= 1) {
        s += __shfl_xor_sync(0xffffffffu, s, o);
        q += __shfl_xor_sync(0xffffffffu, q, o);
    }
    int wid = tid >> 5;
    if ((tid & 31) == 0) { red[wid] = s; red[wid + 4] = q; }
    __syncthreads();
    s = red[0] + red[1] + red[2] + red[3];
    q = red[4] + red[5] + red[6] + red[7];
    const float invC = 1.0f / CH;
    float m = s * invC;
    float rs = rsqrtf(q * invC - m * m + 1e-5f);
#pragma unroll
    for (int i = 0; i < 3; i++) {
        int c = tid + i * 128;
        float o = (v[i] - m) * rs * g[c] + b[c];
        size_t idx = (size_t)l * CH + c;
        split_bf16(o, &g_ln2h[idx], &g_ln2l[idx]);
    }
}

// ---------------- bf16x3 warp-mma GEMM (128x128 CTA tile, K-chunk 32) ------
// EPI 0: kv   A=lnskip  -> g_kv fp32 (+bias)
// EPI 1: proj A=o       -> g_x = skip+xup+acc+bias (winrow->l)
// EPI 2: mlp1 A=ln2     -> g_h1 = gelu(acc+bias) as hi/lo bf16
// EPI 3: mlp2 A=h1      -> out = g_x+acc+bias
#define KC 32
#define APAD 40  // bf16 row stride in smem

template <int EPI, int KT>
__global__ void __launch_bounds__(256, 1)
mma_gemm(const float* __restrict__ bias, const float* __restrict__ e1,
         const float* __restrict__ e2, float* __restrict__ out, int M) {
    const __nv_bfloat16* Ah = (EPI == 0) ? g_lnskip_h : (EPI == 1) ? g_oh : (EPI == 2) ? g_ln2h : g_h1h;
    const __nv_bfloat16* Al = (EPI == 0) ? g_lnskip_l : (EPI == 1) ? g_ol : (EPI == 2) ? g_ln2l : g_h1l;
    const __nv_bfloat16* Bh = (EPI == 0) ? g_wkv_h : (EPI == 1) ? g_wp_h : (EPI == 2) ? g_w1_h : g_w2_h;
    const __nv_bfloat16* Bl = (EPI == 0) ? g_wkv_l : (EPI == 1) ? g_wp_l : (EPI == 2) ? g_w1_l : g_w2_l;

    __shared__ __align__(16) __nv_bfloat16 sAh[128 * APAD];
    __shared__ __align__(16) __nv_bfloat16 sAl[128 * APAD];
    __shared__ __align__(16) __nv_bfloat16 sBh[128 * APAD];
    __shared__ __align__(16) __nv_bfloat16 sBl[128 * APAD];

    int tid = threadIdx.x;
    int lane = tid & 31, wid = tid >> 5;
    int rowBase = blockIdx.y * 128;
    int n0 = blockIdx.x * 128;
    int wm = (wid >> 2) * 64, wn = (wid & 3) * 32;

    float acc[4][4][4];
#pragma unroll
    for (int a = 0; a < 4; a++)
#pragma unroll
        for (int b = 0; b < 4; b++)
#pragma unroll
            for (int c = 0; c < 4; c++) acc[a][b][c] = 0.f;

    uint32_t aAh = smem_u32(sAh), aAl = smem_u32(sAl), aBh = smem_u32(sBh), aBl = smem_u32(sBl);

    // ldmatrix lane addresses (element offsets)
    int aoffA = (lane & 15) * APAD + (lane >> 4) * 8;
    int aoffB = (lane & 7) * APAD + ((lane >> 3) & 1) * 8;  // lanes 0-15 used by x2

    const int NCH = KT / KC;
    for (int ch = 0; ch < NCH; ch++) {
        int kb = ch * KC;
#pragma unroll
        for (int i = 0; i < 2; i++) {
            int v = tid + i * 256;
            int row = v >> 2, c4 = v & 3;
            int r = rowBase + row;
            size_t aoff = (size_t)r * KT + kb + c4 * 8;
            size_t boff = (size_t)(n0 + row) * KT + kb + c4 * 8;
            uint4 va, vl;
            if (r < M) {
                va = *(const uint4*)(Ah + aoff);
                vl = *(const uint4*)(Al + aoff);
            } else {
                va = make_uint4(0, 0, 0, 0);
                vl = make_uint4(0, 0, 0, 0);
            }
            uint4 vbh = *(const uint4*)(Bh + boff);
            uint4 vbl = *(const uint4*)(Bl + boff);
            int so = row * APAD + c4 * 8;
            *(uint4*)(sAh + so) = va;
            *(uint4*)(sAl + so) = vl;
            *(uint4*)(sBh + so) = vbh;
            *(uint4*)(sBl + so) = vbl;
        }
        __syncthreads();
#pragma unroll
        for (int s = 0; s < 2; s++) {
            int k0 = s * 16;
            uint32_t ah[4][4], al[4][4], bh[4][2], bl[4][2];
#pragma unroll
            for (int mf = 0; mf < 4; mf++) {
                uint32_t off = ((wm + mf * 16) * APAD + k0 + aoffA) * 2;
                ldsm_x4(ah[mf], aAh + off);
                ldsm_x4(al[mf], aAl + off);
            }
#pragma unroll
            for (int nf = 0; nf < 4; nf++) {
                uint32_t off = ((wn + nf * 8) * APAD + k0 + aoffB) * 2;
                ldsm_x2(bh[nf], aBh + off);
                ldsm_x2(bl[nf], aBl + off);
            }
#pragma unroll
            for (int mf = 0; mf < 4; mf++)
#pragma unroll
                for (int nf = 0; nf < 4; nf++) {
                    mma_bf16(acc[mf][nf], ah[mf], bh[nf]);
                    mma_bf16(acc[mf][nf], al[mf], bh[nf]);
                    mma_bf16(acc[mf][nf], ah[mf], bl[nf]);
                }
        }
        __syncthreads();
    }

    int lane4 = lane >> 2, lanec = (lane & 3) * 2;
#pragma unroll
    for (int mf = 0; mf < 4; mf++) {
#pragma unroll
        for (int half = 0; half < 2; half++) {
            int row = rowBase + wm + mf * 16 + lane4 + half * 8;
            if (row >= M) continue;
            int l = 0;
            if (EPI == 1) l = winrow_to_l(row);
#pragma unroll
            for (int nf = 0; nf < 4; nf++) {
#pragma unroll
                for (int e = 0; e < 2; e++) {
                    int col = n0 + wn + nf * 8 + lanec + e;
                    float v = acc[mf][nf][half * 2 + e] + bias[col];
                    if (EPI == 0) {
                        g_kv[(size_t)row * 768 + col] = v;
                    } else if (EPI == 1) {
                        size_t idx = (size_t)l * CH + col;
                        g_x[idx] = e1[idx] + e2[idx] + v;
                    } else if (EPI == 2) {
                        float t = tanhf(0.7978845608028654f * (v + 0.044715f * v * v * v));
                        float gv = 0.5f * v * (1.0f + t);
                        size_t idx = (size_t)row * 1536 + col;
                        split_bf16(gv, &g_h1h[idx], &g_h1l[idx]);
                    } else {
                        size_t idx = (size_t)row * CH + col;
                        out[idx] = g_x[idx] + v;
                    }
                }
            }
        }
    }
}

// ---------------- fused window attention (R=2 row blocking) ----------------
#define ATTN_SMEM ((10976 + 11040 + 10976 + 2198 + 8 * 688) * 4)

__global__ void __launch_bounds__(256) attn_kernel(const float* __restrict__ rpb) {
    int win = blockIdx.x, head = blockIdx.y;
    extern __shared__ float sm[];
    float* q_s = sm;
    float* k_s = q_s + 10976;
    float* v_s = k_s + 11040;
    float* bias_s = v_s + 10976;
    float* p_s = bias_s + 2198;
    int tid = threadIdx.x;
    const size_t base = (size_t)win * NTOK;
    for (int idx = tid; idx < NTOK * HD; idx += 256) {
        int j = idx >> 5, d = idx & 31;
        q_s[idx] = g_ln_q[(base + j) * CH + head * HD + d];
        k_s[d * KPAD + j] = g_kv[(base + j) * 768 + head * HD + d];
        v_s[idx] = g_kv[(base + j) * 768 + 384 + head * HD + d];
    }
    for (int idx = tid; idx < 2197; idx += 256)
        bias_s[idx] = rpb[idx * NHEAD + head];
    __syncthreads();

    int lane = tid & 31, wid = tid >> 5;
    float* pw = p_s + wid * 688;
    for (int rp = wid; rp < 172; rp += 8) {
        int r0 = rp * 2, r1 = rp * 2 + 1;
        bool has1 = r1 < NTOK;
        int r1c = has1 ? r1 : r0;
        float qa[32], qb[32];
#pragma unroll
        for (int d = 0; d < 32; d++) {
            qa[d] = q_s[r0 * 32 + d];
            qb[d] = q_s[r1c * 32 + d];
        }
        int pd0 = r0 / 49, ph0 = (r0 / 7) % 7, pw0 = r0 % 7;
        int pd1 = r1c / 49, ph1 = (r1c / 7) % 7, pw1 = r1c % 7;
        float sv0[11], sv1[11];
        float m0 = -1e30f, m1 = -1e30f;
#pragma unroll
        for (int t = 0; t < 11; t++) {
            int j = lane + t * 32;
            if (j < NTOK) {
                int kd = j / 49, kh = (j / 7) % 7, kw = j % 7;
                int bo = (6 - kd) * 169 + (6 - kh) * 13 + (6 - kw);
                float s0 = bias_s[pd0 * 169 + ph0 * 13 + pw0 + bo];
                float s1 = bias_s[pd1 * 169 + ph1 * 13 + pw1 + bo];
#pragma unroll
                for (int d = 0; d < 32; d++) {
                    float kk = k_s[d * KPAD + j];
                    s0 += qa[d] * kk;
                    s1 += qb[d] * kk;
                }
                sv0[t] = s0; sv1[t] = s1;
                m0 = fmaxf(m0, s0); m1 = fmaxf(m1, s1);
            } else { sv0[t] = -1e30f; sv1[t] = -1e30f; }
        }
#pragma unroll
        for (int o = 16; o > 0; o >>= 1) {
            m0 = fmaxf(m0, __shfl_xor_sync(0xffffffffu, m0, o));
            m1 = fmaxf(m1, __shfl_xor_sync(0xffffffffu, m1, o));
        }
        float sum0 = 0.f, sum1 = 0.f;
#pragma unroll
        for (int t = 0; t < 11; t++) {
            int j = lane + t * 32;
            if (j < NTOK) {
                float e0 = __expf(sv0[t] - m0);
                float e1 = __expf(sv1[t] - m1);
                sum0 += e0; sum1 += e1;
                pw[2 * j] = e0;
                pw[2 * j + 1] = e1;
            }
        }
#pragma unroll
        for (int o = 16; o > 0; o >>= 1) {
            sum0 += __shfl_xor_sync(0xffffffffu, sum0, o);
            sum1 += __shfl_xor_sync(0xffffffffu, sum1, o);
        }
        float inv0 = 1.0f / sum0, inv1 = 1.0f / sum1;
        __syncwarp();
        float a0 = 0.f, a1 = 0.f;
#pragma unroll 7
        for (int j = 0; j < NTOK; j++) {
            float2 pp = *(const float2*)(pw + 2 * j);
            float vv = v_s[j * 32 + lane];
            a0 += pp.x * vv;
            a1 += pp.y * vv;
        }
        size_t o0 = (base + r0) * CH + head * HD + lane;
        float val0 = a0 * inv0;
        split_bf16(val0, &g_oh[o0], &g_ol[o0]);
        if (has1) {
            size_t o1 = (base + r1) * CH + head * HD + lane;
            float val1 = a1 * inv1;
            split_bf16(val1, &g_oh[o1], &g_ol[o1]);
        }
        __syncwarp();
    }
}

// ---------------- launch ----------------
extern "C" void kernel_launch(void* const* d_in, const int* in_sizes, int n_in,
                              void* d_out, int out_size) {
    const float* skip = (const float*)d_in[0];
    const float* xup  = (const float*)d_in[1];
    const float* ln1g = (const float*)d_in[5];
    const float* ln1b = (const float*)d_in[6];
    const float* kvw  = (const float*)d_in[7];
    const float* kvb  = (const float*)d_in[8];
    const float* rpb  = (const float*)d_in[9];
    const float* pw   = (const float*)d_in[10];
    const float* pb   = (const float*)d_in[11];
    const float* ln2g = (const float*)d_in[12];
    const float* ln2b = (const float*)d_in[13];
    const float* w1   = (const float*)d_in[14];
    const float* b1   = (const float*)d_in[15];
    const float* w2   = (const float*)d_in[16];
    const float* b2   = (const float*)d_in[17];
    float* out = (float*)d_out;

    cudaFuncSetAttribute(attn_kernel, cudaFuncAttributeMaxDynamicSharedMemorySize, ATTN_SMEM);

    wconv<0><<<dim3(768 / 32, 384 / 32), dim3(32, 8)>>>(kvw, 384, 768);
    wconv<1><<<dim3(384 / 32, 384 / 32), dim3(32, 8)>>>(pw, 384, 384);
    wconv<2><<<dim3(1536 / 32, 384 / 32), dim3(32, 8)>>>(w1, 384, 1536);
    wconv<3><<<dim3(384 / 32, 1536 / 32), dim3(32, 8)>>>(w2, 1536, 384);

    ln1_kernel<<<LTOT, 128>>>(skip, xup, ln1g, ln1b);
    mma_gemm<0, 384><<<dim3(6, 172), 256>>>(kvb, nullptr, nullptr, nullptr, LTOT);
    attn_kernel<<<dim3(NWIN, NHEAD), 256, ATTN_SMEM>>>(rpb);
    mma_gemm<1, 384><<<dim3(3, 172), 256>>>(pb, skip, xup, nullptr, LTOT);
    ln2_kernel<<<LTOT, 128>>>(ln2g, ln2b);
    mma_gemm<2, 384><<<dim3(12, 172), 256>>>(b1, nullptr, nullptr, nullptr, LTOT);
    mma_gemm<3, 1536><<<dim3(3, 172), 256>>>(b2, nullptr, nullptr, out, LTOT);
}

// round 10
// speedup vs baseline: 1.8500x; 1.1476x over previous
#include <cuda_runtime.h>
#include <cuda_bf16.h>
#include <cstdint>
#include <math.h>

// Problem constants (B=1, D=H=W=28, C=384, NH=12, WS=7)
#define LTOT  21952
#define CH    384
#define NWIN  64
#define NTOK  343
#define NHEAD 12
#define HD    32
#define KPAD  345

// ---------------- scratch ----------------
__device__ float g_ln_q[LTOT * CH];
__device__ __nv_bfloat16 g_lnskip_h[LTOT * CH], g_lnskip_l[LTOT * CH];
__device__ float g_kv[LTOT * 2 * CH];
__device__ __nv_bfloat16 g_oh[LTOT * CH], g_ol[LTOT * CH];
__device__ float g_x[LTOT * CH];
__device__ __nv_bfloat16 g_ln2h[LTOT * CH], g_ln2l[LTOT * CH];
__device__ __nv_bfloat16 g_h1h[LTOT * 4 * CH], g_h1l[LTOT * 4 * CH];
__device__ __nv_bfloat16 g_wkv_h[768 * 384], g_wkv_l[768 * 384];
__device__ __nv_bfloat16 g_wp_h[384 * 384], g_wp_l[384 * 384];
__device__ __nv_bfloat16 g_w1_h[1536 * 384], g_w1_l[1536 * 384];
__device__ __nv_bfloat16 g_w2_h[384 * 1536], g_w2_l[384 * 1536];

__device__ __forceinline__ int l_to_winrow(int l) {
    int d = l / 784, rem = l % 784, h = rem / 28, w = rem % 28;
    int win = (d / 7) * 16 + (h / 7) * 4 + (w / 7);
    int p = (d % 7) * 49 + (h % 7) * 7 + (w % 7);
    return win * NTOK + p;
}
__device__ __forceinline__ int winrow_to_l(int r) {
    int win = r / NTOK, p = r % NTOK;
    int wd = win >> 4, wh = (win >> 2) & 3, ww = win & 3;
    int pd = p / 49, ph = (p / 7) % 7, pw = p % 7;
    return (wd * 7 + pd) * 784 + (wh * 7 + ph) * 28 + (ww * 7 + pw);
}
__device__ __forceinline__ void split_bf16(float v, __nv_bfloat16* h, __nv_bfloat16* l) {
    __nv_bfloat16 hh = __float2bfloat16(v);
    *h = hh;
    *l = __float2bfloat16(v - __bfloat162float(hh));
}

// ---------------- mma.sync helpers ----------------
__device__ __forceinline__ uint32_t smem_u32(const void* p) {
    uint32_t a;
    asm("{ .reg .u64 t; cvta.to.shared.u64 t, %1; cvt.u32.u64 %0, t; }" : "=r"(a) : "l"(p));
    return a;
}
__device__ __forceinline__ void ldsm_x4(uint32_t* r, uint32_t addr) {
    asm volatile("ldmatrix.sync.aligned.m8n8.x4.shared.b16 {%0,%1,%2,%3}, [%4];"
                 : "=r"(r[0]), "=r"(r[1]), "=r"(r[2]), "=r"(r[3]) : "r"(addr));
}
__device__ __forceinline__ void ldsm_x2(uint32_t* r, uint32_t addr) {
    asm volatile("ldmatrix.sync.aligned.m8n8.x2.shared.b16 {%0,%1}, [%2];"
                 : "=r"(r[0]), "=r"(r[1]) : "r"(addr));
}
__device__ __forceinline__ void mma_bf16(float* d, const uint32_t* a, const uint32_t* b) {
    asm volatile(
        "mma.sync.aligned.m16n8k16.row.col.f32.bf16.bf16.f32 "
        "{%0,%1,%2,%3}, {%4,%5,%6,%7}, {%8,%9}, {%0,%1,%2,%3};"
        : "+f"(d[0]), "+f"(d[1]), "+f"(d[2]), "+f"(d[3])
        : "r"(a[0]), "r"(a[1]), "r"(a[2]), "r"(a[3]), "r"(b[0]), "r"(b[1]));
}
__device__ __forceinline__ void cp_async16(uint32_t dst, const void* src, int pbytes) {
    asm volatile("cp.async.cg.shared.global [%0], [%1], 16, %2;"
                 :: "r"(dst), "l"(src), "r"(pbytes) : "memory");
}

// ---------------- weight transpose + hi/lo convert: Th[n][k] = W[k][n] ------
template <int WID>
__global__ void wconv(const float* __restrict__ W, int K, int N) {
    __nv_bfloat16* Th = (WID == 0) ? g_wkv_h : (WID == 1) ? g_wp_h : (WID == 2) ? g_w1_h : g_w2_h;
    __nv_bfloat16* Tl = (WID == 0) ? g_wkv_l : (WID == 1) ? g_wp_l : (WID == 2) ? g_w1_l : g_w2_l;
    __shared__ float t[32][33];
    int nb = blockIdx.x * 32, kb = blockIdx.y * 32;
    int tx = threadIdx.x, ty = threadIdx.y;
#pragma unroll
    for (int i = 0; i < 4; i++) {
        int k = ty + i * 8;
        t[k][tx] = W[(size_t)(kb + k) * N + nb + tx];
    }
    __syncthreads();
#pragma unroll
    for (int i = 0; i < 4; i++) {
        int nrow = ty + i * 8;
        float v = t[tx][nrow];
        size_t o = (size_t)(nb + nrow) * K + kb + tx;
        split_bf16(v, &Th[o], &Tl[o]);
    }
}

// ---------------- LN1 ----------------
__global__ void ln1_kernel(const float* __restrict__ skip, const float* __restrict__ xup,
                           const float* __restrict__ g, const float* __restrict__ b) {
    int l = blockIdx.x;
    int tid = threadIdx.x;
    __shared__ float red[16];
    const float* sp = skip + (size_t)l * CH;
    const float* xp = xup + (size_t)l * CH;
    float v1[3], v2[3];
    float s1 = 0.f, q1 = 0.f, s2 = 0.f, q2 = 0.f;
#pragma unroll
    for (int i = 0; i < 3; i++) {
        int c = tid + i * 128;
        v1[i] = sp[c]; v2[i] = xp[c];
        s1 += v1[i]; q1 += v1[i] * v1[i];
        s2 += v2[i]; q2 += v2[i] * v2[i];
    }
#pragma unroll
    for (int o = 16; o > 0; o >>= 1) {
        s1 += __shfl_xor_sync(0xffffffffu, s1, o);
        q1 += __shfl_xor_sync(0xffffffffu, q1, o);
        s2 += __shfl_xor_sync(0xffffffffu, s2, o);
        q2 += __shfl_xor_sync(0xffffffffu, q2, o);
    }
    int wid = tid >> 5;
    if ((tid & 31) == 0) { red[wid] = s1; red[wid + 4] = q1; red[wid + 8] = s2; red[wid + 12] = q2; }
    __syncthreads();
    s1 = red[0] + red[1] + red[2] + red[3];
    q1 = red[4] + red[5] + red[6] + red[7];
    s2 = red[8] + red[9] + red[10] + red[11];
    q2 = red[12] + red[13] + red[14] + red[15];
    const float invC = 1.0f / CH;
    float m1 = s1 * invC, m2 = s2 * invC;
    float r1 = rsqrtf(q1 * invC - m1 * m1 + 1e-5f);
    float r2 = rsqrtf(q2 * invC - m2 * m2 + 1e-5f);
    int r = l_to_winrow(l);
    const float QS = 0.17677669529663687f;
#pragma unroll
    for (int i = 0; i < 3; i++) {
        int c = tid + i * 128;
        float gg = g[c], bb = b[c];
        float o1 = (v1[i] - m1) * r1 * gg + bb;
        size_t idx = (size_t)r * CH + c;
        split_bf16(o1, &g_lnskip_h[idx], &g_lnskip_l[idx]);
        g_ln_q[idx] = ((v2[i] - m2) * r2 * gg + bb) * QS;
    }
}

// ---------------- LN2 ----------------
__global__ void ln2_kernel(const float* __restrict__ g, const float* __restrict__ b) {
    int l = blockIdx.x;
    int tid = threadIdx.x;
    __shared__ float red[8];
    const float* xp = g_x + (size_t)l * CH;
    float v[3];
    float s = 0.f, q = 0.f;
#pragma unroll
    for (int i = 0; i < 3; i++) {
        v[i] = xp[tid + i * 128];
        s += v[i]; q += v[i] * v[i];
    }
#pragma unroll
    for (int o = 16; o > 0; o >>= 1) {
        s += __shfl_xor_sync(0xffffffffu, s, o);
        q += __shfl_xor_sync(0xffffffffu, q, o);
    }
    int wid = tid >> 5;
    if ((tid & 31) == 0) { red[wid] = s; red[wid + 4] = q; }
    __syncthreads();
    s = red[0] + red[1] + red[2] + red[3];
    q = red[4] + red[5] + red[6] + red[7];
    const float invC = 1.0f / CH;
    float m = s * invC;
    float rs = rsqrtf(q * invC - m * m + 1e-5f);
#pragma unroll
    for (int i = 0; i < 3; i++) {
        int c = tid + i * 128;
        float o = (v[i] - m) * rs * g[c] + b[c];
        size_t idx = (size_t)l * CH + c;
        split_bf16(o, &g_ln2h[idx], &g_ln2l[idx]);
    }
}

// ------- bf16x3 warp-mma GEMM, cp.async double-buffered (128x128, KC=32) ----
#define KC 32
#define APAD 40
#define ARR_BYTES (128 * APAD * 2)         // 10240
#define STAGE_BYTES (4 * ARR_BYTES)        // 40960
#define GEMM_SMEM (2 * STAGE_BYTES)        // 81920

template <int EPI, int KT>
__global__ void __launch_bounds__(256, 1)
mma_gemm(const float* __restrict__ bias, const float* __restrict__ e1,
         const float* __restrict__ e2, float* __restrict__ out, int M) {
    const __nv_bfloat16* Ah = (EPI == 0) ? g_lnskip_h : (EPI == 1) ? g_oh : (EPI == 2) ? g_ln2h : g_h1h;
    const __nv_bfloat16* Al = (EPI == 0) ? g_lnskip_l : (EPI == 1) ? g_ol : (EPI == 2) ? g_ln2l : g_h1l;
    const __nv_bfloat16* Bh = (EPI == 0) ? g_wkv_h : (EPI == 1) ? g_wp_h : (EPI == 2) ? g_w1_h : g_w2_h;
    const __nv_bfloat16* Bl = (EPI == 0) ? g_wkv_l : (EPI == 1) ? g_wp_l : (EPI == 2) ? g_w1_l : g_w2_l;

    extern __shared__ __align__(16) char dsm[];
    uint32_t sb = smem_u32(dsm);

    int tid = threadIdx.x;
    int lane = tid & 31, wid = tid >> 5;
    int rowBase = blockIdx.y * 128;
    int n0 = blockIdx.x * 128;
    int wm = (wid >> 2) * 64, wn = (wid & 3) * 32;

    float acc[4][4][4];
#pragma unroll
    for (int a = 0; a < 4; a++)
#pragma unroll
        for (int b = 0; b < 4; b++)
#pragma unroll
            for (int c = 0; c < 4; c++) acc[a][b][c] = 0.f;

    // per-thread load slots: 2 rows of 8 bf16 per array
    int lrow0 = tid >> 2, lc0 = (tid & 3);          // v = tid
    int lrow1 = (tid + 256) >> 2, lc1 = (tid & 3);  // v = tid+256
    uint32_t so0 = (uint32_t)(lrow0 * APAD + lc0 * 8) * 2;
    uint32_t so1 = (uint32_t)(lrow1 * APAD + lc1 * 8) * 2;

    auto issue_chunk = [&](int ch, int stage) {
        int kb = ch * KC;
        uint32_t sbase = sb + stage * STAGE_BYTES;
        // slot 0
        {
            int r = rowBase + lrow0;
            bool v = r < M;
            const __nv_bfloat16* pa = Ah + ((size_t)(v ? r : 0) * KT + kb + lc0 * 8);
            const __nv_bfloat16* pl = Al + ((size_t)(v ? r : 0) * KT + kb + lc0 * 8);
            cp_async16(sbase + so0, pa, v ? 16 : 0);
            cp_async16(sbase + ARR_BYTES + so0, pl, v ? 16 : 0);
            const __nv_bfloat16* pbh = Bh + ((size_t)(n0 + lrow0) * KT + kb + lc0 * 8);
            const __nv_bfloat16* pbl = Bl + ((size_t)(n0 + lrow0) * KT + kb + lc0 * 8);
            cp_async16(sbase + 2 * ARR_BYTES + so0, pbh, 16);
            cp_async16(sbase + 3 * ARR_BYTES + so0, pbl, 16);
        }
        // slot 1
        {
            int r = rowBase + lrow1;
            bool v = r < M;
            const __nv_bfloat16* pa = Ah + ((size_t)(v ? r : 0) * KT + kb + lc1 * 8);
            const __nv_bfloat16* pl = Al + ((size_t)(v ? r : 0) * KT + kb + lc1 * 8);
            cp_async16(sbase + so1, pa, v ? 16 : 0);
            cp_async16(sbase + ARR_BYTES + so1, pl, v ? 16 : 0);
            const __nv_bfloat16* pbh = Bh + ((size_t)(n0 + lrow1) * KT + kb + lc1 * 8);
            const __nv_bfloat16* pbl = Bl + ((size_t)(n0 + lrow1) * KT + kb + lc1 * 8);
            cp_async16(sbase + 2 * ARR_BYTES + so1, pbh, 16);
            cp_async16(sbase + 3 * ARR_BYTES + so1, pbl, 16);
        }
        asm volatile("cp.async.commit_group;" ::: "memory");
    };

    int aoffA = (lane & 15) * APAD + (lane >> 4) * 8;
    int aoffB = (lane & 7) * APAD + ((lane >> 3) & 1) * 8;

    const int NCH = KT / KC;
    issue_chunk(0, 0);
    for (int ch = 0; ch < NCH; ch++) {
        int cur = ch & 1;
        if (ch + 1 < NCH) {
            issue_chunk(ch + 1, cur ^ 1);
            asm volatile("cp.async.wait_group 1;" ::: "memory");
        } else {
            asm volatile("cp.async.wait_group 0;" ::: "memory");
        }
        __syncthreads();
        uint32_t aAh = sb + cur * STAGE_BYTES;
        uint32_t aAl = aAh + ARR_BYTES;
        uint32_t aBh = aAh + 2 * ARR_BYTES;
        uint32_t aBl = aAh + 3 * ARR_BYTES;
#pragma unroll
        for (int s = 0; s < 2; s++) {
            int k0 = s * 16;
            uint32_t ah[4][4], al[4][4], bh[4][2], bl[4][2];
#pragma unroll
            for (int mf = 0; mf < 4; mf++) {
                uint32_t off = ((wm + mf * 16) * APAD + k0 + aoffA) * 2;
                ldsm_x4(ah[mf], aAh + off);
                ldsm_x4(al[mf], aAl + off);
            }
#pragma unroll
            for (int nf = 0; nf < 4; nf++) {
                uint32_t off = ((wn + nf * 8) * APAD + k0 + aoffB) * 2;
                ldsm_x2(bh[nf], aBh + off);
                ldsm_x2(bl[nf], aBl + off);
            }
#pragma unroll
            for (int mf = 0; mf < 4; mf++)
#pragma unroll
                for (int nf = 0; nf < 4; nf++) {
                    mma_bf16(acc[mf][nf], ah[mf], bh[nf]);
                    mma_bf16(acc[mf][nf], al[mf], bh[nf]);
                    mma_bf16(acc[mf][nf], ah[mf], bl[nf]);
                }
        }
        __syncthreads();
    }

    int lane4 = lane >> 2, lanec = (lane & 3) * 2;
#pragma unroll
    for (int mf = 0; mf < 4; mf++) {
#pragma unroll
        for (int half = 0; half < 2; half++) {
            int row = rowBase + wm + mf * 16 + lane4 + half * 8;
            if (row >= M) continue;
            int l = 0;
            if (EPI == 1) l = winrow_to_l(row);
#pragma unroll
            for (int nf = 0; nf < 4; nf++) {
#pragma unroll
                for (int e = 0; e < 2; e++) {
                    int col = n0 + wn + nf * 8 + lanec + e;
                    float v = acc[mf][nf][half * 2 + e] + bias[col];
                    if (EPI == 0) {
                        g_kv[(size_t)row * 768 + col] = v;
                    } else if (EPI == 1) {
                        size_t idx = (size_t)l * CH + col;
                        g_x[idx] = e1[idx] + e2[idx] + v;
                    } else if (EPI == 2) {
                        float t = tanhf(0.7978845608028654f * (v + 0.044715f * v * v * v));
                        float gv = 0.5f * v * (1.0f + t);
                        size_t idx = (size_t)row * 1536 + col;
                        split_bf16(gv, &g_h1h[idx], &g_h1l[idx]);
                    } else {
                        size_t idx = (size_t)row * CH + col;
                        out[idx] = g_x[idx] + v;
                    }
                }
            }
        }
    }
}

// ---------------- fused window attention (R=2, bf16x2 packed probs) --------
#define ATHREADS 512
#define NWARP 16
#define ATTN_SMEM ((10976 + 11040 + 10976 + 2198) * 4 + NWARP * 344 * 4)

__global__ void __launch_bounds__(ATHREADS) attn_kernel(const float* __restrict__ rpb) {
    int win = blockIdx.x, head = blockIdx.y;
    extern __shared__ float sm[];
    float* q_s = sm;
    float* k_s = q_s + 10976;
    float* v_s = k_s + 11040;
    float* bias_s = v_s + 10976;
    __nv_bfloat162* pall = (__nv_bfloat162*)(bias_s + 2198);
    int tid = threadIdx.x;
    const size_t base = (size_t)win * NTOK;
    for (int idx = tid; idx < NTOK * HD; idx += ATHREADS) {
        int j = idx >> 5, d = idx & 31;
        q_s[idx] = g_ln_q[(base + j) * CH + head * HD + d];
        k_s[d * KPAD + j] = g_kv[(base + j) * 768 + head * HD + d];
        v_s[idx] = g_kv[(base + j) * 768 + 384 + head * HD + d];
    }
    for (int idx = tid; idx < 2197; idx += ATHREADS)
        bias_s[idx] = rpb[idx * NHEAD + head];
    __syncthreads();

    int lane = tid & 31, wid = tid >> 5;
    __nv_bfloat162* pw = pall + wid * 344;
    for (int rp = wid; rp < 172; rp += NWARP) {
        int r0 = rp * 2, r1 = rp * 2 + 1;
        bool has1 = r1 < NTOK;
        int r1c = has1 ? r1 : r0;
        float qa[32], qb[32];
#pragma unroll
        for (int i = 0; i < 8; i++) {
            float4 t0 = *(const float4*)(q_s + r0 * 32 + i * 4);
            float4 t1 = *(const float4*)(q_s + r1c * 32 + i * 4);
            qa[i * 4 + 0] = t0.x; qa[i * 4 + 1] = t0.y; qa[i * 4 + 2] = t0.z; qa[i * 4 + 3] = t0.w;
            qb[i * 4 + 0] = t1.x; qb[i * 4 + 1] = t1.y; qb[i * 4 + 2] = t1.z; qb[i * 4 + 3] = t1.w;
        }
        int pd0 = r0 / 49, ph0 = (r0 / 7) % 7, pw0 = r0 % 7;
        int pd1 = r1c / 49, ph1 = (r1c / 7) % 7, pw1 = r1c % 7;
        float sv0[11], sv1[11];
        float m0 = -1e30f, m1 = -1e30f;
#pragma unroll
        for (int t = 0; t < 11; t++) {
            int j = lane + t * 32;
            if (j < NTOK) {
                int kd = j / 49, kh = (j / 7) % 7, kw = j % 7;
                int bo = (6 - kd) * 169 + (6 - kh) * 13 + (6 - kw);
                float s0 = bias_s[pd0 * 169 + ph0 * 13 + pw0 + bo];
                float s1 = bias_s[pd1 * 169 + ph1 * 13 + pw1 + bo];
#pragma unroll
                for (int d = 0; d < 32; d++) {
                    float kk = k_s[d * KPAD + j];
                    s0 += qa[d] * kk;
                    s1 += qb[d] * kk;
                }
                sv0[t] = s0; sv1[t] = s1;
                m0 = fmaxf(m0, s0); m1 = fmaxf(m1, s1);
            } else { sv0[t] = -1e30f; sv1[t] = -1e30f; }
        }
#pragma unroll
        for (int o = 16; o > 0; o >>= 1) {
            m0 = fmaxf(m0, __shfl_xor_sync(0xffffffffu, m0, o));
            m1 = fmaxf(m1, __shfl_xor_sync(0xffffffffu, m1, o));
        }
        float sum0 = 0.f, sum1 = 0.f;
#pragma unroll
        for (int t = 0; t < 11; t++) {
            int j = lane + t * 32;
            if (j < NTOK) {
                float e0 = __expf(sv0[t] - m0);
                float e1 = __expf(sv1[t] - m1);
                sum0 += e0; sum1 += e1;
                pw[j] = __floats2bfloat162_rn(e0, e1);
            }
        }
#pragma unroll
        for (int o = 16; o > 0; o >>= 1) {
            sum0 += __shfl_xor_sync(0xffffffffu, sum0, o);
            sum1 += __shfl_xor_sync(0xffffffffu, sum1, o);
        }
        float inv0 = 1.0f / sum0, inv1 = 1.0f / sum1;
        __syncwarp();
        float a0 = 0.f, a1 = 0.f;
#pragma unroll 7
        for (int j = 0; j < NTOK; j++) {
            float2 p = __bfloat1622float2(pw[j]);
            float vv = v_s[j * 32 + lane];
            a0 = fmaf(p.x, vv, a0);
            a1 = fmaf(p.y, vv, a1);
        }
        size_t o0 = (base + r0) * CH + head * HD + lane;
        float val0 = a0 * inv0;
        split_bf16(val0, &g_oh[o0], &g_ol[o0]);
        if (has1) {
            size_t o1 = (base + r1) * CH + head * HD + lane;
            float val1 = a1 * inv1;
            split_bf16(val1, &g_ol[o1] == nullptr ? &g_oh[o1] : &g_oh[o1], &g_ol[o1]);
        }
        __syncwarp();
    }
}

// ---------------- launch ----------------
extern "C" void kernel_launch(void* const* d_in, const int* in_sizes, int n_in,
                              void* d_out, int out_size) {
    const float* skip = (const float*)d_in[0];
    const float* xup  = (const float*)d_in[1];
    const float* ln1g = (const float*)d_in[5];
    const float* ln1b = (const float*)d_in[6];
    const float* kvw  = (const float*)d_in[7];
    const float* kvb  = (const float*)d_in[8];
    const float* rpb  = (const float*)d_in[9];
    const float* pw   = (const float*)d_in[10];
    const float* pb   = (const float*)d_in[11];
    const float* ln2g = (const float*)d_in[12];
    const float* ln2b = (const float*)d_in[13];
    const float* w1   = (const float*)d_in[14];
    const float* b1   = (const float*)d_in[15];
    const float* w2   = (const float*)d_in[16];
    const float* b2   = (const float*)d_in[17];
    float* out = (float*)d_out;

    cudaFuncSetAttribute(attn_kernel, cudaFuncAttributeMaxDynamicSharedMemorySize, ATTN_SMEM);
    cudaFuncSetAttribute(mma_gemm<0, 384>, cudaFuncAttributeMaxDynamicSharedMemorySize, GEMM_SMEM);
    cudaFuncSetAttribute(mma_gemm<1, 384>, cudaFuncAttributeMaxDynamicSharedMemorySize, GEMM_SMEM);
    cudaFuncSetAttribute(mma_gemm<2, 384>, cudaFuncAttributeMaxDynamicSharedMemorySize, GEMM_SMEM);
    cudaFuncSetAttribute(mma_gemm<3, 1536>, cudaFuncAttributeMaxDynamicSharedMemorySize, GEMM_SMEM);

    wconv<0><<<dim3(768 / 32, 384 / 32), dim3(32, 8)>>>(kvw, 384, 768);
    wconv<1><<<dim3(384 / 32, 384 / 32), dim3(32, 8)>>>(pw, 384, 384);
    wconv<2><<<dim3(1536 / 32, 384 / 32), dim3(32, 8)>>>(w1, 384, 1536);
    wconv<3><<<dim3(384 / 32, 1536 / 32), dim3(32, 8)>>>(w2, 1536, 384);

    ln1_kernel<<<LTOT, 128>>>(skip, xup, ln1g, ln1b);
    mma_gemm<0, 384><<<dim3(6, 172), 256, GEMM_SMEM>>>(kvb, nullptr, nullptr, nullptr, LTOT);
    attn_kernel<<<dim3(NWIN, NHEAD), ATHREADS, ATTN_SMEM>>>(rpb);
    mma_gemm<1, 384><<<dim3(3, 172), 256, GEMM_SMEM>>>(pb, skip, xup, nullptr, LTOT);
    ln2_kernel<<<LTOT, 128>>>(ln2g, ln2b);
    mma_gemm<2, 384><<<dim3(12, 172), 256, GEMM_SMEM>>>(b1, nullptr, nullptr, nullptr, LTOT);
    mma_gemm<3, 1536><<<dim3(3, 172), 256, GEMM_SMEM>>>(b2, nullptr, nullptr, out, LTOT);
}

// round 11
// speedup vs baseline: 1.8833x; 1.0180x over previous
#include <cuda_runtime.h>
#include <cuda_bf16.h>
#include <cuda_fp16.h>
#include <cstdint>
#include <math.h>

// Problem constants (B=1, D=H=W=28, C=384, NH=12, WS=7)
#define LTOT  21952
#define CH    384
#define NWIN  64
#define NTOK  343
#define NHEAD 12
#define HD    32
#define KPAD  345

// ---------------- scratch ----------------
__device__ float g_ln_q[LTOT * CH];
__device__ __nv_bfloat16 g_lnskip_h[LTOT * CH], g_lnskip_l[LTOT * CH];
__device__ float g_kv[LTOT * 2 * CH];
__device__ __nv_bfloat16 g_oh[LTOT * CH], g_ol[LTOT * CH];
__device__ float g_x[LTOT * CH];
__device__ __nv_bfloat16 g_ln2h[LTOT * CH], g_ln2l[LTOT * CH];
__device__ __nv_bfloat16 g_h1h[LTOT * 4 * CH], g_h1l[LTOT * 4 * CH];
__device__ __nv_bfloat16 g_wkv_h[768 * 384], g_wkv_l[768 * 384];
__device__ __nv_bfloat16 g_wp_h[384 * 384], g_wp_l[384 * 384];
__device__ __nv_bfloat16 g_w1_h[1536 * 384], g_w1_l[1536 * 384];
__device__ __nv_bfloat16 g_w2_h[384 * 1536], g_w2_l[384 * 1536];

__device__ __forceinline__ int l_to_winrow(int l) {
    int d = l / 784, rem = l % 784, h = rem / 28, w = rem % 28;
    int win = (d / 7) * 16 + (h / 7) * 4 + (w / 7);
    int p = (d % 7) * 49 + (h % 7) * 7 + (w % 7);
    return win * NTOK + p;
}
__device__ __forceinline__ int winrow_to_l(int r) {
    int win = r / NTOK, p = r % NTOK;
    int wd = win >> 4, wh = (win >> 2) & 3, ww = win & 3;
    int pd = p / 49, ph = (p / 7) % 7, pw = p % 7;
    return (wd * 7 + pd) * 784 + (wh * 7 + ph) * 28 + (ww * 7 + pw);
}
__device__ __forceinline__ void split_bf16(float v, __nv_bfloat16* h, __nv_bfloat16* l) {
    __nv_bfloat16 hh = __float2bfloat16(v);
    *h = hh;
    *l = __float2bfloat16(v - __bfloat162float(hh));
}

// ---------------- mma.sync helpers ----------------
__device__ __forceinline__ uint32_t smem_u32(const void* p) {
    uint32_t a;
    asm("{ .reg .u64 t; cvta.to.shared.u64 t, %1; cvt.u32.u64 %0, t; }" : "=r"(a) : "l"(p));
    return a;
}
__device__ __forceinline__ void ldsm_x4(uint32_t* r, uint32_t addr) {
    asm volatile("ldmatrix.sync.aligned.m8n8.x4.shared.b16 {%0,%1,%2,%3}, [%4];"
                 : "=r"(r[0]), "=r"(r[1]), "=r"(r[2]), "=r"(r[3]) : "r"(addr));
}
__device__ __forceinline__ void ldsm_x2(uint32_t* r, uint32_t addr) {
    asm volatile("ldmatrix.sync.aligned.m8n8.x2.shared.b16 {%0,%1}, [%2];"
                 : "=r"(r[0]), "=r"(r[1]) : "r"(addr));
}
__device__ __forceinline__ void mma_bf16(float* d, const uint32_t* a, const uint32_t* b) {
    asm volatile(
        "mma.sync.aligned.m16n8k16.row.col.f32.bf16.bf16.f32 "
        "{%0,%1,%2,%3}, {%4,%5,%6,%7}, {%8,%9}, {%0,%1,%2,%3};"
        : "+f"(d[0]), "+f"(d[1]), "+f"(d[2]), "+f"(d[3])
        : "r"(a[0]), "r"(a[1]), "r"(a[2]), "r"(a[3]), "r"(b[0]), "r"(b[1]));
}
__device__ __forceinline__ void cp_async16(uint32_t dst, const void* src, int pbytes) {
    asm volatile("cp.async.cg.shared.global [%0], [%1], 16, %2;"
                 :: "r"(dst), "l"(src), "r"(pbytes) : "memory");
}

// ---------------- weight transpose + hi/lo convert: Th[n][k] = W[k][n] ------
template <int WID>
__global__ void wconv(const float* __restrict__ W, int K, int N) {
    __nv_bfloat16* Th = (WID == 0) ? g_wkv_h : (WID == 1) ? g_wp_h : (WID == 2) ? g_w1_h : g_w2_h;
    __nv_bfloat16* Tl = (WID == 0) ? g_wkv_l : (WID == 1) ? g_wp_l : (WID == 2) ? g_w1_l : g_w2_l;
    __shared__ float t[32][33];
    int nb = blockIdx.x * 32, kb = blockIdx.y * 32;
    int tx = threadIdx.x, ty = threadIdx.y;
#pragma unroll
    for (int i = 0; i < 4; i++) {
        int k = ty + i * 8;
        t[k][tx] = W[(size_t)(kb + k) * N + nb + tx];
    }
    __syncthreads();
#pragma unroll
    for (int i = 0; i < 4; i++) {
        int nrow = ty + i * 8;
        float v = t[tx][nrow];
        size_t o = (size_t)(nb + nrow) * K + kb + tx;
        split_bf16(v, &Th[o], &Tl[o]);
    }
}

// ---------------- LN1 ----------------
__global__ void ln1_kernel(const float* __restrict__ skip, const float* __restrict__ xup,
                           const float* __restrict__ g, const float* __restrict__ b) {
    int l = blockIdx.x;
    int tid = threadIdx.x;
    __shared__ float red[16];
    const float* sp = skip + (size_t)l * CH;
    const float* xp = xup + (size_t)l * CH;
    float v1[3], v2[3];
    float s1 = 0.f, q1 = 0.f, s2 = 0.f, q2 = 0.f;
#pragma unroll
    for (int i = 0; i < 3; i++) {
        int c = tid + i * 128;
        v1[i] = sp[c]; v2[i] = xp[c];
        s1 += v1[i]; q1 += v1[i] * v1[i];
        s2 += v2[i]; q2 += v2[i] * v2[i];
    }
#pragma unroll
    for (int o = 16; o > 0; o >>= 1) {
        s1 += __shfl_xor_sync(0xffffffffu, s1, o);
        q1 += __shfl_xor_sync(0xffffffffu, q1, o);
        s2 += __shfl_xor_sync(0xffffffffu, s2, o);
        q2 += __shfl_xor_sync(0xffffffffu, q2, o);
    }
    int wid = tid >> 5;
    if ((tid & 31) == 0) { red[wid] = s1; red[wid + 4] = q1; red[wid + 8] = s2; red[wid + 12] = q2; }
    __syncthreads();
    s1 = red[0] + red[1] + red[2] + red[3];
    q1 = red[4] + red[5] + red[6] + red[7];
    s2 = red[8] + red[9] + red[10] + red[11];
    q2 = red[12] + red[13] + red[14] + red[15];
    const float invC = 1.0f / CH;
    float m1 = s1 * invC, m2 = s2 * invC;
    float r1 = rsqrtf(q1 * invC - m1 * m1 + 1e-5f);
    float r2 = rsqrtf(q2 * invC - m2 * m2 + 1e-5f);
    int r = l_to_winrow(l);
    // hd^-0.5 * log2(e): scores produced directly in log2 domain
    const float QS = 0.25504626814056f;
#pragma unroll
    for (int i = 0; i < 3; i++) {
        int c = tid + i * 128;
        float gg = g[c], bb = b[c];
        float o1 = (v1[i] - m1) * r1 * gg + bb;
        size_t idx = (size_t)r * CH + c;
        split_bf16(o1, &g_lnskip_h[idx], &g_lnskip_l[idx]);
        g_ln_q[idx] = ((v2[i] - m2) * r2 * gg + bb) * QS;
    }
}

// ---------------- LN2 ----------------
__global__ void ln2_kernel(const float* __restrict__ g, const float* __restrict__ b) {
    int l = blockIdx.x;
    int tid = threadIdx.x;
    __shared__ float red[8];
    const float* xp = g_x + (size_t)l * CH;
    float v[3];
    float s = 0.f, q = 0.f;
#pragma unroll
    for (int i = 0; i < 3; i++) {
        v[i] = xp[tid + i * 128];
        s += v[i]; q += v[i] * v[i];
    }
#pragma unroll
    for (int o = 16; o > 0; o >>= 1) {
        s += __shfl_xor_sync(0xffffffffu, s, o);
        q += __shfl_xor_sync(0xffffffffu, q, o);
    }
    int wid = tid >> 5;
    if ((tid & 31) == 0) { red[wid] = s; red[wid + 4] = q; }
    __syncthreads();
    s = red[0] + red[1] + red[2] + red[3];
    q = red[4] + red[5] + red[6] + red[7];
    const float invC = 1.0f / CH;
    float m = s * invC;
    float rs = rsqrtf(q * invC - m * m + 1e-5f);
#pragma unroll
    for (int i = 0; i < 3; i++) {
        int c = tid + i * 128;
        float o = (v[i] - m) * rs * g[c] + b[c];
        size_t idx = (size_t)l * CH + c;
        split_bf16(o, &g_ln2h[idx], &g_ln2l[idx]);
    }
}

// ------- bf16x3 warp-mma GEMM, cp.async double-buffered (128x128, KC=32) ----
#define KC 32
#define APAD 40
#define ARR_BYTES (128 * APAD * 2)         // 10240
#define STAGE_BYTES (4 * ARR_BYTES)        // 40960
#define GEMM_SMEM (2 * STAGE_BYTES)        // 81920

template <int EPI, int KT>
__global__ void __launch_bounds__(256, 1)
mma_gemm(const float* __restrict__ bias, const float* __restrict__ e1,
         const float* __restrict__ e2, float* __restrict__ out, int M) {
    const __nv_bfloat16* Ah = (EPI == 0) ? g_lnskip_h : (EPI == 1) ? g_oh : (EPI == 2) ? g_ln2h : g_h1h;
    const __nv_bfloat16* Al = (EPI == 0) ? g_lnskip_l : (EPI == 1) ? g_ol : (EPI == 2) ? g_ln2l : g_h1l;
    const __nv_bfloat16* Bh = (EPI == 0) ? g_wkv_h : (EPI == 1) ? g_wp_h : (EPI == 2) ? g_w1_h : g_w2_h;
    const __nv_bfloat16* Bl = (EPI == 0) ? g_wkv_l : (EPI == 1) ? g_wp_l : (EPI == 2) ? g_w1_l : g_w2_l;

    extern __shared__ __align__(16) char dsm[];
    uint32_t sb = smem_u32(dsm);

    int tid = threadIdx.x;
    int lane = tid & 31, wid = tid >> 5;
    int rowBase = blockIdx.y * 128;
    int n0 = blockIdx.x * 128;
    int wm = (wid >> 2) * 64, wn = (wid & 3) * 32;

    float acc[4][4][4];
#pragma unroll
    for (int a = 0; a < 4; a++)
#pragma unroll
        for (int b = 0; b < 4; b++)
#pragma unroll
            for (int c = 0; c < 4; c++) acc[a][b][c] = 0.f;

    int lrow0 = tid >> 2, lc0 = (tid & 3);
    int lrow1 = (tid + 256) >> 2, lc1 = (tid & 3);
    uint32_t so0 = (uint32_t)(lrow0 * APAD + lc0 * 8) * 2;
    uint32_t so1 = (uint32_t)(lrow1 * APAD + lc1 * 8) * 2;

    auto issue_chunk = [&](int ch, int stage) {
        int kb = ch * KC;
        uint32_t sbase = sb + stage * STAGE_BYTES;
        {
            int r = rowBase + lrow0;
            bool v = r < M;
            const __nv_bfloat16* pa = Ah + ((size_t)(v ? r : 0) * KT + kb + lc0 * 8);
            const __nv_bfloat16* pl = Al + ((size_t)(v ? r : 0) * KT + kb + lc0 * 8);
            cp_async16(sbase + so0, pa, v ? 16 : 0);
            cp_async16(sbase + ARR_BYTES + so0, pl, v ? 16 : 0);
            const __nv_bfloat16* pbh = Bh + ((size_t)(n0 + lrow0) * KT + kb + lc0 * 8);
            const __nv_bfloat16* pbl = Bl + ((size_t)(n0 + lrow0) * KT + kb + lc0 * 8);
            cp_async16(sbase + 2 * ARR_BYTES + so0, pbh, 16);
            cp_async16(sbase + 3 * ARR_BYTES + so0, pbl, 16);
        }
        {
            int r = rowBase + lrow1;
            bool v = r < M;
            const __nv_bfloat16* pa = Ah + ((size_t)(v ? r : 0) * KT + kb + lc1 * 8);
            const __nv_bfloat16* pl = Al + ((size_t)(v ? r : 0) * KT + kb + lc1 * 8);
            cp_async16(sbase + so1, pa, v ? 16 : 0);
            cp_async16(sbase + ARR_BYTES + so1, pl, v ? 16 : 0);
            const __nv_bfloat16* pbh = Bh + ((size_t)(n0 + lrow1) * KT + kb + lc1 * 8);
            const __nv_bfloat16* pbl = Bl + ((size_t)(n0 + lrow1) * KT + kb + lc1 * 8);
            cp_async16(sbase + 2 * ARR_BYTES + so1, pbh, 16);
            cp_async16(sbase + 3 * ARR_BYTES + so1, pbl, 16);
        }
        asm volatile("cp.async.commit_group;" ::: "memory");
    };

    int aoffA = (lane & 15) * APAD + (lane >> 4) * 8;
    int aoffB = (lane & 7) * APAD + ((lane >> 3) & 1) * 8;

    const int NCH = KT / KC;
    issue_chunk(0, 0);
    for (int ch = 0; ch < NCH; ch++) {
        int cur = ch & 1;
        if (ch + 1 < NCH) {
            issue_chunk(ch + 1, cur ^ 1);
            asm volatile("cp.async.wait_group 1;" ::: "memory");
        } else {
            asm volatile("cp.async.wait_group 0;" ::: "memory");
        }
        __syncthreads();
        uint32_t aAh = sb + cur * STAGE_BYTES;
        uint32_t aAl = aAh + ARR_BYTES;
        uint32_t aBh = aAh + 2 * ARR_BYTES;
        uint32_t aBl = aAh + 3 * ARR_BYTES;
#pragma unroll
        for (int s = 0; s < 2; s++) {
            int k0 = s * 16;
            uint32_t ah[4][4], al[4][4], bh[4][2], bl[4][2];
#pragma unroll
            for (int mf = 0; mf < 4; mf++) {
                uint32_t off = ((wm + mf * 16) * APAD + k0 + aoffA) * 2;
                ldsm_x4(ah[mf], aAh + off);
                ldsm_x4(al[mf], aAl + off);
            }
#pragma unroll
            for (int nf = 0; nf < 4; nf++) {
                uint32_t off = ((wn + nf * 8) * APAD + k0 + aoffB) * 2;
                ldsm_x2(bh[nf], aBh + off);
                ldsm_x2(bl[nf], aBl + off);
            }
#pragma unroll
            for (int mf = 0; mf < 4; mf++)
#pragma unroll
                for (int nf = 0; nf < 4; nf++) {
                    mma_bf16(acc[mf][nf], ah[mf], bh[nf]);
                    mma_bf16(acc[mf][nf], al[mf], bh[nf]);
                    mma_bf16(acc[mf][nf], ah[mf], bl[nf]);
                }
        }
        __syncthreads();
    }

    int lane4 = lane >> 2, lanec = (lane & 3) * 2;
#pragma unroll
    for (int mf = 0; mf < 4; mf++) {
#pragma unroll
        for (int half = 0; half < 2; half++) {
            int row = rowBase + wm + mf * 16 + lane4 + half * 8;
            if (row >= M) continue;
            int l = 0;
            if (EPI == 1) l = winrow_to_l(row);
#pragma unroll
            for (int nf = 0; nf < 4; nf++) {
#pragma unroll
                for (int e = 0; e < 2; e++) {
                    int col = n0 + wn + nf * 8 + lanec + e;
                    float v = acc[mf][nf][half * 2 + e] + bias[col];
                    if (EPI == 0) {
                        g_kv[(size_t)row * 768 + col] = v;
                    } else if (EPI == 1) {
                        size_t idx = (size_t)l * CH + col;
                        g_x[idx] = e1[idx] + e2[idx] + v;
                    } else if (EPI == 2) {
                        float t = tanhf(0.7978845608028654f * (v + 0.044715f * v * v * v));
                        float gv = 0.5f * v * (1.0f + t);
                        size_t idx = (size_t)row * 1536 + col;
                        split_bf16(gv, &g_h1h[idx], &g_h1l[idx]);
                    } else {
                        size_t idx = (size_t)row * CH + col;
                        out[idx] = g_x[idx] + v;
                    }
                }
            }
        }
    }
}

// ------- fused window attention (R=2, log2-domain scores, f16x2 exp2) ------
#define ATHREADS 512
#define NWARP 16
#define ATTN_SMEM ((10976 + 11040 + 10976 + 2198) * 4 + NWARP * 344 * 4)

__global__ void __launch_bounds__(ATHREADS) attn_kernel(const float* __restrict__ rpb) {
    int win = blockIdx.x, head = blockIdx.y;
    extern __shared__ float sm[];
    float* q_s = sm;
    float* k_s = q_s + 10976;
    float* v_s = k_s + 11040;
    float* bias_s = v_s + 10976;
    __half2* pall = (__half2*)(bias_s + 2198);
    int tid = threadIdx.x;
    const size_t base = (size_t)win * NTOK;
    const float LOG2E = 1.4426950408889634f;
    for (int idx = tid; idx < NTOK * HD; idx += ATHREADS) {
        int j = idx >> 5, d = idx & 31;
        q_s[idx] = g_ln_q[(base + j) * CH + head * HD + d];
        k_s[d * KPAD + j] = g_kv[(base + j) * 768 + head * HD + d];
        v_s[idx] = g_kv[(base + j) * 768 + 384 + head * HD + d];
    }
    for (int idx = tid; idx < 2197; idx += ATHREADS)
        bias_s[idx] = rpb[idx * NHEAD + head] * LOG2E;
    __syncthreads();

    int lane = tid & 31, wid = tid >> 5;
    __half2* pw = pall + wid * 344;
    for (int rp = wid; rp < 172; rp += NWARP) {
        int r0 = rp * 2, r1 = rp * 2 + 1;
        bool has1 = r1 < NTOK;
        int r1c = has1 ? r1 : r0;
        float qa[32], qb[32];
#pragma unroll
        for (int i = 0; i < 8; i++) {
            float4 t0 = *(const float4*)(q_s + r0 * 32 + i * 4);
            float4 t1 = *(const float4*)(q_s + r1c * 32 + i * 4);
            qa[i * 4 + 0] = t0.x; qa[i * 4 + 1] = t0.y; qa[i * 4 + 2] = t0.z; qa[i * 4 + 3] = t0.w;
            qb[i * 4 + 0] = t1.x; qb[i * 4 + 1] = t1.y; qb[i * 4 + 2] = t1.z; qb[i * 4 + 3] = t1.w;
        }
        int pd0 = r0 / 49, ph0 = (r0 / 7) % 7, pw0 = r0 % 7;
        int pd1 = r1c / 49, ph1 = (r1c / 7) % 7, pw1 = r1c % 7;
        float sv0[11], sv1[11];
        float m0 = -1e30f, m1 = -1e30f;
#pragma unroll
        for (int t = 0; t < 11; t++) {
            int j = lane + t * 32;
            if (j < NTOK) {
                int kd = j / 49, kh = (j / 7) % 7, kw = j % 7;
                int bo = (6 - kd) * 169 + (6 - kh) * 13 + (6 - kw);
                float s0 = bias_s[pd0 * 169 + ph0 * 13 + pw0 + bo];
                float s1 = bias_s[pd1 * 169 + ph1 * 13 + pw1 + bo];
#pragma unroll
                for (int d = 0; d < 32; d++) {
                    float kk = k_s[d * KPAD + j];
                    s0 += qa[d] * kk;
                    s1 += qb[d] * kk;
                }
                sv0[t] = s0; sv1[t] = s1;
                m0 = fmaxf(m0, s0); m1 = fmaxf(m1, s1);
            } else { sv0[t] = -1e30f; sv1[t] = -1e30f; }
        }
#pragma unroll
        for (int o = 16; o > 0; o >>= 1) {
            m0 = fmaxf(m0, __shfl_xor_sync(0xffffffffu, m0, o));
            m1 = fmaxf(m1, __shfl_xor_sync(0xffffffffu, m1, o));
        }
        float sum0 = 0.f, sum1 = 0.f;
#pragma unroll
        for (int t = 0; t < 11; t++) {
            int j = lane + t * 32;
            if (j < NTOK) {
                // scores already in log2 domain: p = exp2(s - m), two rows per MUFU op
                __half2 hx = __floats2half2_rn(sv0[t] - m0, sv1[t] - m1);
                __half2 hp = h2exp2(hx);
                pw[j] = hp;
                float2 f = __half22float2(hp);
                sum0 += f.x; sum1 += f.y;
            }
        }
#pragma unroll
        for (int o = 16; o > 0; o >>= 1) {
            sum0 += __shfl_xor_sync(0xffffffffu, sum0, o);
            sum1 += __shfl_xor_sync(0xffffffffu, sum1, o);
        }
        float inv0 = 1.0f / sum0, inv1 = 1.0f / sum1;
        __syncwarp();
        float a0 = 0.f, a1 = 0.f;
#pragma unroll 7
        for (int j = 0; j < NTOK; j++) {
            float2 p = __half22float2(pw[j]);
            float vv = v_s[j * 32 + lane];
            a0 = fmaf(p.x, vv, a0);
            a1 = fmaf(p.y, vv, a1);
        }
        size_t o0 = (base + r0) * CH + head * HD + lane;
        float val0 = a0 * inv0;
        split_bf16(val0, &g_oh[o0], &g_ol[o0]);
        if (has1) {
            size_t o1 = (base + r1) * CH + head * HD + lane;
            float val1 = a1 * inv1;
            split_bf16(val1, &g_oh[o1], &g_ol[o1]);
        }
        __syncwarp();
    }
}

// ---------------- launch ----------------
extern "C" void kernel_launch(void* const* d_in, const int* in_sizes, int n_in,
                              void* d_out, int out_size) {
    const float* skip = (const float*)d_in[0];
    const float* xup  = (const float*)d_in[1];
    const float* ln1g = (const float*)d_in[5];
    const float* ln1b = (const float*)d_in[6];
    const float* kvw  = (const float*)d_in[7];
    const float* kvb  = (const float*)d_in[8];
    const float* rpb  = (const float*)d_in[9];
    const float* pw   = (const float*)d_in[10];
    const float* pb   = (const float*)d_in[11];
    const float* ln2g = (const float*)d_in[12];
    const float* ln2b = (const float*)d_in[13];
    const float* w1   = (const float*)d_in[14];
    const float* b1   = (const float*)d_in[15];
    const float* w2   = (const float*)d_in[16];
    const float* b2   = (const float*)d_in[17];
    float* out = (float*)d_out;

    cudaFuncSetAttribute(attn_kernel, cudaFuncAttributeMaxDynamicSharedMemorySize, ATTN_SMEM);
    cudaFuncSetAttribute(mma_gemm<0, 384>, cudaFuncAttributeMaxDynamicSharedMemorySize, GEMM_SMEM);
    cudaFuncSetAttribute(mma_gemm<1, 384>, cudaFuncAttributeMaxDynamicSharedMemorySize, GEMM_SMEM);
    cudaFuncSetAttribute(mma_gemm<2, 384>, cudaFuncAttributeMaxDynamicSharedMemorySize, GEMM_SMEM);
    cudaFuncSetAttribute(mma_gemm<3, 1536>, cudaFuncAttributeMaxDynamicSharedMemorySize, GEMM_SMEM);

    wconv<0><<<dim3(768 / 32, 384 / 32), dim3(32, 8)>>>(kvw, 384, 768);
    wconv<1><<<dim3(384 / 32, 384 / 32), dim3(32, 8)>>>(pw, 384, 384);
    wconv<2><<<dim3(1536 / 32, 384 / 32), dim3(32, 8)>>>(w1, 384, 1536);
    wconv<3><<<dim3(384 / 32, 1536 / 32), dim3(32, 8)>>>(w2, 1536, 384);

    ln1_kernel<<<LTOT, 128>>>(skip, xup, ln1g, ln1b);
    mma_gemm<0, 384><<<dim3(6, 172), 256, GEMM_SMEM>>>(kvb, nullptr, nullptr, nullptr, LTOT);
    attn_kernel<<<dim3(NWIN, NHEAD), ATHREADS, ATTN_SMEM>>>(rpb);
    mma_gemm<1, 384><<<dim3(3, 172), 256, GEMM_SMEM>>>(pb, skip, xup, nullptr, LTOT);
    ln2_kernel<<<LTOT, 128>>>(ln2g, ln2b);
    mma_gemm<2, 384><<<dim3(12, 172), 256, GEMM_SMEM>>>(b1, nullptr, nullptr, nullptr, LTOT);
    mma_gemm<3, 1536><<<dim3(3, 172), 256, GEMM_SMEM>>>(b2, nullptr, nullptr, out, LTOT);
}

// round 13
// speedup vs baseline: 2.1219x; 1.1267x over previous
#include <cuda_runtime.h>
#include <cuda_bf16.h>
#include <cuda_fp16.h>
#include <cstdint>
#include <math.h>

// Problem constants (B=1, D=H=W=28, C=384, NH=12, WS=7)
#define LTOT  21952
#define CH    384
#define NWIN  64
#define NTOK  343
#define NHEAD 12
#define HD    32
#define KPAD  345

// ---------------- scratch ----------------
__device__ float g_ln_q[LTOT * CH];
__device__ __half g_lnskip_h[LTOT * CH], g_lnskip_l[LTOT * CH];
__device__ float g_kv[LTOT * 2 * CH];
__device__ __half g_oh[LTOT * CH], g_ol[LTOT * CH];
__device__ float g_x[LTOT * CH];
__device__ __half g_ln2h[LTOT * CH], g_ln2l[LTOT * CH];
__device__ __half g_h1h[LTOT * 4 * CH], g_h1l[LTOT * 4 * CH];
__device__ __half g_wkv[768 * 384];
__device__ __half g_wp[384 * 384];
__device__ __half g_w1[1536 * 384];
__device__ __half g_w2[384 * 1536];

__device__ __forceinline__ int l_to_winrow(int l) {
    int d = l / 784, rem = l % 784, h = rem / 28, w = rem % 28;
    int win = (d / 7) * 16 + (h / 7) * 4 + (w / 7);
    int p = (d % 7) * 49 + (h % 7) * 7 + (w % 7);
    return win * NTOK + p;
}
__device__ __forceinline__ int winrow_to_l(int r) {
    int win = r / NTOK, p = r % NTOK;
    int wd = win >> 4, wh = (win >> 2) & 3, ww = win & 3;
    int pd = p / 49, ph = (p / 7) % 7, pw = p % 7;
    return (wd * 7 + pd) * 784 + (wh * 7 + ph) * 28 + (ww * 7 + pw);
}
__device__ __forceinline__ void split_half(float v, __half* h, __half* l) {
    __half hh = __float2half_rn(v);
    *h = hh;
    *l = __float2half_rn(v - __half2float(hh));
}

// ---------------- mma.sync helpers ----------------
__device__ __forceinline__ uint32_t smem_u32(const void* p) {
    uint32_t a;
    asm("{ .reg .u64 t; cvta.to.shared.u64 t, %1; cvt.u32.u64 %0, t; }" : "=r"(a) : "l"(p));
    return a;
}
__device__ __forceinline__ void ldsm_x4(uint32_t* r, uint32_t addr) {
    asm volatile("ldmatrix.sync.aligned.m8n8.x4.shared.b16 {%0,%1,%2,%3}, [%4];"
                 : "=r"(r[0]), "=r"(r[1]), "=r"(r[2]), "=r"(r[3]) : "r"(addr));
}
__device__ __forceinline__ void ldsm_x2(uint32_t* r, uint32_t addr) {
    asm volatile("ldmatrix.sync.aligned.m8n8.x2.shared.b16 {%0,%1}, [%2];"
                 : "=r"(r[0]), "=r"(r[1]) : "r"(addr));
}
__device__ __forceinline__ void mma_f16(float* d, const uint32_t* a, const uint32_t* b) {
    asm volatile(
        "mma.sync.aligned.m16n8k16.row.col.f32.f16.f16.f32 "
        "{%0,%1,%2,%3}, {%4,%5,%6,%7}, {%8,%9}, {%0,%1,%2,%3};"
        : "+f"(d[0]), "+f"(d[1]), "+f"(d[2]), "+f"(d[3])
        : "r"(a[0]), "r"(a[1]), "r"(a[2]), "r"(a[3]), "r"(b[0]), "r"(b[1]));
}
__device__ __forceinline__ void cp_async16(uint32_t dst, const void* src, int pbytes) {
    asm volatile("cp.async.cg.shared.global [%0], [%1], 16, %2;"
                 :: "r"(dst), "l"(src), "r"(pbytes) : "memory");
}

// ---------------- weight transpose + fp16 convert: T[n][k] = W[k][n] -------
template <int WID>
__global__ void wconv(const float* __restrict__ W, int K, int N) {
    __half* T = (WID == 0) ? g_wkv : (WID == 1) ? g_wp : (WID == 2) ? g_w1 : g_w2;
    __shared__ float t[32][33];
    int nb = blockIdx.x * 32, kb = blockIdx.y * 32;
    int tx = threadIdx.x, ty = threadIdx.y;
#pragma unroll
    for (int i = 0; i < 4; i++) {
        int k = ty + i * 8;
        t[k][tx] = W[(size_t)(kb + k) * N + nb + tx];
    }
    __syncthreads();
#pragma unroll
    for (int i = 0; i < 4; i++) {
        int nrow = ty + i * 8;
        T[(size_t)(nb + nrow) * K + kb + tx] = __float2half_rn(t[tx][nrow]);
    }
}

// ---------------- LN1 ----------------
__global__ void ln1_kernel(const float* __restrict__ skip, const float* __restrict__ xup,
                           const float* __restrict__ g, const float* __restrict__ b) {
    int l = blockIdx.x;
    int tid = threadIdx.x;
    __shared__ float red[16];
    const float* sp = skip + (size_t)l * CH;
    const float* xp = xup + (size_t)l * CH;
    float v1[3], v2[3];
    float s1 = 0.f, q1 = 0.f, s2 = 0.f, q2 = 0.f;
#pragma unroll
    for (int i = 0; i < 3; i++) {
        int c = tid + i * 128;
        v1[i] = sp[c]; v2[i] = xp[c];
        s1 += v1[i]; q1 += v1[i] * v1[i];
        s2 += v2[i]; q2 += v2[i] * v2[i];
    }
#pragma unroll
    for (int o = 16; o > 0; o >>= 1) {
        s1 += __shfl_xor_sync(0xffffffffu, s1, o);
        q1 += __shfl_xor_sync(0xffffffffu, q1, o);
        s2 += __shfl_xor_sync(0xffffffffu, s2, o);
        q2 += __shfl_xor_sync(0xffffffffu, q2, o);
    }
    int wid = tid >> 5;
    if ((tid & 31) == 0) { red[wid] = s1; red[wid + 4] = q1; red[wid + 8] = s2; red[wid + 12] = q2; }
    __syncthreads();
    s1 = red[0] + red[1] + red[2] + red[3];
    q1 = red[4] + red[5] + red[6] + red[7];
    s2 = red[8] + red[9] + red[10] + red[11];
    q2 = red[12] + red[13] + red[14] + red[15];
    const float invC = 1.0f / CH;
    float m1 = s1 * invC, m2 = s2 * invC;
    float r1 = rsqrtf(q1 * invC - m1 * m1 + 1e-5f);
    float r2 = rsqrtf(q2 * invC - m2 * m2 + 1e-5f);
    int r = l_to_winrow(l);
    // hd^-0.5 * log2(e): scores produced directly in log2 domain
    const float QS = 0.25504626814056f;
#pragma unroll
    for (int i = 0; i < 3; i++) {
        int c = tid + i * 128;
        float gg = g[c], bb = b[c];
        float o1 = (v1[i] - m1) * r1 * gg + bb;
        size_t idx = (size_t)r * CH + c;
        split_half(o1, &g_lnskip_h[idx], &g_lnskip_l[idx]);
        g_ln_q[idx] = ((v2[i] - m2) * r2 * gg + bb) * QS;
    }
}

// ---------------- LN2 ----------------
__global__ void ln2_kernel(const float* __restrict__ g, const float* __restrict__ b) {
    int l = blockIdx.x;
    int tid = threadIdx.x;
    __shared__ float red[8];
    const float* xp = g_x + (size_t)l * CH;
    float v[3];
    float s = 0.f, q = 0.f;
#pragma unroll
    for (int i = 0; i < 3; i++) {
        v[i] = xp[tid + i * 128];
        s += v[i]; q += v[i] * v[i];
    }
#pragma unroll
    for (int o = 16; o > 0; o >>= 1) {
        s += __shfl_xor_sync(0xffffffffu, s, o);
        q += __shfl_xor_sync(0xffffffffu, q, o);
    }
    int wid = tid >> 5;
    if ((tid & 31) == 0) { red[wid] = s; red[wid + 4] = q; }
    __syncthreads();
    s = red[0] + red[1] + red[2] + red[3];
    q = red[4] + red[5] + red[6] + red[7];
    const float invC = 1.0f / CH;
    float m = s * invC;
    float rs = rsqrtf(q * invC - m * m + 1e-5f);
#pragma unroll
    for (int i = 0; i < 3; i++) {
        int c = tid + i * 128;
        float o = (v[i] - m) * rs * g[c] + b[c];
        size_t idx = (size_t)l * CH + c;
        split_half(o, &g_ln2h[idx], &g_ln2l[idx]);
    }
}

// ------- fp16x2 warp-mma GEMM, cp.async double-buffered (128x128, KC=32) ---
// A = activations as exact (hi + lo) fp16 pair; B = weights as single fp16.
#define KC 32
#define APAD 40
#define ARR_BYTES (128 * APAD * 2)         // 10240
#define STAGE_BYTES (3 * ARR_BYTES)        // 30720
#define GEMM_SMEM (2 * STAGE_BYTES)        // 61440

template <int EPI, int KT>
__global__ void __launch_bounds__(256, 1)
mma_gemm(const float* __restrict__ bias, const float* __restrict__ e1,
         const float* __restrict__ e2, float* __restrict__ out, int M) {
    const __half* Ah = (EPI == 0) ? g_lnskip_h : (EPI == 1) ? g_oh : (EPI == 2) ? g_ln2h : g_h1h;
    const __half* Al = (EPI == 0) ? g_lnskip_l : (EPI == 1) ? g_ol : (EPI == 2) ? g_ln2l : g_h1l;
    const __half* B  = (EPI == 0) ? g_wkv : (EPI == 1) ? g_wp : (EPI == 2) ? g_w1 : g_w2;

    extern __shared__ __align__(16) char dsm[];
    uint32_t sb = smem_u32(dsm);

    int tid = threadIdx.x;
    int lane = tid & 31, wid = tid >> 5;
    int rowBase = blockIdx.y * 128;
    int n0 = blockIdx.x * 128;
    int wm = (wid >> 2) * 64, wn = (wid & 3) * 32;

    float acc[4][4][4];
#pragma unroll
    for (int a = 0; a < 4; a++)
#pragma unroll
        for (int b = 0; b < 4; b++)
#pragma unroll
            for (int c = 0; c < 4; c++) acc[a][b][c] = 0.f;

    int lrow0 = tid >> 2, lc0 = (tid & 3);
    int lrow1 = (tid + 256) >> 2, lc1 = (tid & 3);
    uint32_t so0 = (uint32_t)(lrow0 * APAD + lc0 * 8) * 2;
    uint32_t so1 = (uint32_t)(lrow1 * APAD + lc1 * 8) * 2;

    auto issue_chunk = [&](int ch, int stage) {
        int kb = ch * KC;
        uint32_t sbase = sb + stage * STAGE_BYTES;
        {
            int r = rowBase + lrow0;
            bool v = r < M;
            const __half* pa = Ah + ((size_t)(v ? r : 0) * KT + kb + lc0 * 8);
            const __half* pl = Al + ((size_t)(v ? r : 0) * KT + kb + lc0 * 8);
            cp_async16(sbase + so0, pa, v ? 16 : 0);
            cp_async16(sbase + ARR_BYTES + so0, pl, v ? 16 : 0);
            const __half* pb = B + ((size_t)(n0 + lrow0) * KT + kb + lc0 * 8);
            cp_async16(sbase + 2 * ARR_BYTES + so0, pb, 16);
        }
        {
            int r = rowBase + lrow1;
            bool v = r < M;
            const __half* pa = Ah + ((size_t)(v ? r : 0) * KT + kb + lc1 * 8);
            const __half* pl = Al + ((size_t)(v ? r : 0) * KT + kb + lc1 * 8);
            cp_async16(sbase + so1, pa, v ? 16 : 0);
            cp_async16(sbase + ARR_BYTES + so1, pl, v ? 16 : 0);
            const __half* pb = B + ((size_t)(n0 + lrow1) * KT + kb + lc1 * 8);
            cp_async16(sbase + 2 * ARR_BYTES + so1, pb, 16);
        }
        asm volatile("cp.async.commit_group;" ::: "memory");
    };

    int aoffA = (lane & 15) * APAD + (lane >> 4) * 8;
    int aoffB = (lane & 7) * APAD + ((lane >> 3) & 1) * 8;

    const int NCH = KT / KC;
    issue_chunk(0, 0);
    for (int ch = 0; ch < NCH; ch++) {
        int cur = ch & 1;
        if (ch + 1 < NCH) {
            issue_chunk(ch + 1, cur ^ 1);
            asm volatile("cp.async.wait_group 1;" ::: "memory");
        } else {
            asm volatile("cp.async.wait_group 0;" ::: "memory");
        }
        __syncthreads();
        uint32_t aAh = sb + cur * STAGE_BYTES;
        uint32_t aAl = aAh + ARR_BYTES;
        uint32_t aB  = aAh + 2 * ARR_BYTES;
#pragma unroll
        for (int s = 0; s < 2; s++) {
            int k0 = s * 16;
            uint32_t ah[4][4], al[4][4], bh[4][2];
#pragma unroll
            for (int mf = 0; mf < 4; mf++) {
                uint32_t off = ((wm + mf * 16) * APAD + k0 + aoffA) * 2;
                ldsm_x4(ah[mf], aAh + off);
                ldsm_x4(al[mf], aAl + off);
            }
#pragma unroll
            for (int nf = 0; nf < 4; nf++) {
                uint32_t off = ((wn + nf * 8) * APAD + k0 + aoffB) * 2;
                ldsm_x2(bh[nf], aB + off);
            }
#pragma unroll
            for (int mf = 0; mf < 4; mf++)
#pragma unroll
                for (int nf = 0; nf < 4; nf++) {
                    mma_f16(acc[mf][nf], ah[mf], bh[nf]);
                    mma_f16(acc[mf][nf], al[mf], bh[nf]);
                }
        }
        __syncthreads();
    }

    int lane4 = lane >> 2, lanec = (lane & 3) * 2;
#pragma unroll
    for (int mf = 0; mf < 4; mf++) {
#pragma unroll
        for (int half = 0; half < 2; half++) {
            int row = rowBase + wm + mf * 16 + lane4 + half * 8;
            if (row >= M) continue;
            int l = 0;
            if (EPI == 1) l = winrow_to_l(row);
#pragma unroll
            for (int nf = 0; nf < 4; nf++) {
#pragma unroll
                for (int e = 0; e < 2; e++) {
                    int col = n0 + wn + nf * 8 + lanec + e;
                    float v = acc[mf][nf][half * 2 + e] + bias[col];
                    if (EPI == 0) {
                        g_kv[(size_t)row * 768 + col] = v;
                    } else if (EPI == 1) {
                        size_t idx = (size_t)l * CH + col;
                        g_x[idx] = e1[idx] + e2[idx] + v;
                    } else if (EPI == 2) {
                        float t = tanhf(0.7978845608028654f * (v + 0.044715f * v * v * v));
                        float gv = 0.5f * v * (1.0f + t);
                        size_t idx = (size_t)row * 1536 + col;
                        split_half(gv, &g_h1h[idx], &g_h1l[idx]);
                    } else {
                        size_t idx = (size_t)row * CH + col;
                        out[idx] = g_x[idx] + v;
                    }
                }
            }
        }
    }
}

// ------- fused window attention (R=2, log2-domain scores, f16x2 exp2) ------
#define ATHREADS 512
#define NWARP 16
#define ATTN_SMEM ((10976 + 11040 + 10976 + 2198) * 4 + NWARP * 344 * 4)

__global__ void __launch_bounds__(ATHREADS) attn_kernel(const float* __restrict__ rpb) {
    int win = blockIdx.x, head = blockIdx.y;
    extern __shared__ float sm[];
    float* q_s = sm;
    float* k_s = q_s + 10976;
    float* v_s = k_s + 11040;
    float* bias_s = v_s + 10976;
    __half2* pall = (__half2*)(bias_s + 2198);
    int tid = threadIdx.x;
    const size_t base = (size_t)win * NTOK;
    const float LOG2E = 1.4426950408889634f;
    for (int idx = tid; idx < NTOK * HD; idx += ATHREADS) {
        int j = idx >> 5, d = idx & 31;
        q_s[idx] = g_ln_q[(base + j) * CH + head * HD + d];
        k_s[d * KPAD + j] = g_kv[(base + j) * 768 + head * HD + d];
        v_s[idx] = g_kv[(base + j) * 768 + 384 + head * HD + d];
    }
    for (int idx = tid; idx < 2197; idx += ATHREADS)
        bias_s[idx] = rpb[idx * NHEAD + head] * LOG2E;
    __syncthreads();

    int lane = tid & 31, wid = tid >> 5;
    __half2* pw = pall + wid * 344;
    for (int rp = wid; rp < 172; rp += NWARP) {
        int r0 = rp * 2, r1 = rp * 2 + 1;
        bool has1 = r1 < NTOK;
        int r1c = has1 ? r1 : r0;
        float qa[32], qb[32];
#pragma unroll
        for (int i = 0; i < 8; i++) {
            float4 t0 = *(const float4*)(q_s + r0 * 32 + i * 4);
            float4 t1 = *(const float4*)(q_s + r1c * 32 + i * 4);
            qa[i * 4 + 0] = t0.x; qa[i * 4 + 1] = t0.y; qa[i * 4 + 2] = t0.z; qa[i * 4 + 3] = t0.w;
            qb[i * 4 + 0] = t1.x; qb[i * 4 + 1] = t1.y; qb[i * 4 + 2] = t1.z; qb[i * 4 + 3] = t1.w;
        }
        int pd0 = r0 / 49, ph0 = (r0 / 7) % 7, pw0 = r0 % 7;
        int pd1 = r1c / 49, ph1 = (r1c / 7) % 7, pw1 = r1c % 7;
        float sv0[11], sv1[11];
        float m0 = -1e30f, m1 = -1e30f;
#pragma unroll
        for (int t = 0; t < 11; t++) {
            int j = lane + t * 32;
            if (j < NTOK) {
                int kd = j / 49, kh = (j / 7) % 7, kw = j % 7;
                int bo = (6 - kd) * 169 + (6 - kh) * 13 + (6 - kw);
                float s0 = bias_s[pd0 * 169 + ph0 * 13 + pw0 + bo];
                float s1 = bias_s[pd1 * 169 + ph1 * 13 + pw1 + bo];
#pragma unroll
                for (int d = 0; d < 32; d++) {
                    float kk = k_s[d * KPAD + j];
                    s0 += qa[d] * kk;
                    s1 += qb[d] * kk;
                }
                sv0[t] = s0; sv1[t] = s1;
                m0 = fmaxf(m0, s0); m1 = fmaxf(m1, s1);
            } else { sv0[t] = -1e30f; sv1[t] = -1e30f; }
        }
#pragma unroll
        for (int o = 16; o > 0; o >>= 1) {
            m0 = fmaxf(m0, __shfl_xor_sync(0xffffffffu, m0, o));
            m1 = fmaxf(m1, __shfl_xor_sync(0xffffffffu, m1, o));
        }
        float sum0 = 0.f, sum1 = 0.f;
#pragma unroll
        for (int t = 0; t < 11; t++) {
            int j = lane + t * 32;
            if (j < NTOK) {
                __half2 hx = __floats2half2_rn(sv0[t] - m0, sv1[t] - m1);
                __half2 hp = h2exp2(hx);
                pw[j] = hp;
                float2 f = __half22float2(hp);
                sum0 += f.x; sum1 += f.y;
            }
        }
#pragma unroll
        for (int o = 16; o > 0; o >>= 1) {
            sum0 += __shfl_xor_sync(0xffffffffu, sum0, o);
            sum1 += __shfl_xor_sync(0xffffffffu, sum1, o);
        }
        float inv0 = 1.0f / sum0, inv1 = 1.0f / sum1;
        __syncwarp();
        float a0 = 0.f, a1 = 0.f;
#pragma unroll 7
        for (int j = 0; j < NTOK; j++) {
            float2 p = __half22float2(pw[j]);
            float vv = v_s[j * 32 + lane];
            a0 = fmaf(p.x, vv, a0);
            a1 = fmaf(p.y, vv, a1);
        }
        size_t o0 = (base + r0) * CH + head * HD + lane;
        float val0 = a0 * inv0;
        split_half(val0, &g_oh[o0], &g_ol[o0]);
        if (has1) {
            size_t o1 = (base + r1) * CH + head * HD + lane;
            float val1 = a1 * inv1;
            split_half(val1, &g_oh[o1], &g_ol[o1]);
        }
        __syncwarp();
    }
}

// ---------------- launch ----------------
extern "C" void kernel_launch(void* const* d_in, const int* in_sizes, int n_in,
                              void* d_out, int out_size) {
    const float* skip = (const float*)d_in[0];
    const float* xup  = (const float*)d_in[1];
    const float* ln1g = (const float*)d_in[5];
    const float* ln1b = (const float*)d_in[6];
    const float* kvw  = (const float*)d_in[7];
    const float* kvb  = (const float*)d_in[8];
    const float* rpb  = (const float*)d_in[9];
    const float* pw   = (const float*)d_in[10];
    const float* pb   = (const float*)d_in[11];
    const float* ln2g = (const float*)d_in[12];
    const float* ln2b = (const float*)d_in[13];
    const float* w1   = (const float*)d_in[14];
    const float* b1   = (const float*)d_in[15];
    const float* w2   = (const float*)d_in[16];
    const float* b2   = (const float*)d_in[17];
    float* out = (float*)d_out;

    cudaFuncSetAttribute(attn_kernel, cudaFuncAttributeMaxDynamicSharedMemorySize, ATTN_SMEM);
    cudaFuncSetAttribute(mma_gemm<0, 384>, cudaFuncAttributeMaxDynamicSharedMemorySize, GEMM_SMEM);
    cudaFuncSetAttribute(mma_gemm<1, 384>, cudaFuncAttributeMaxDynamicSharedMemorySize, GEMM_SMEM);
    cudaFuncSetAttribute(mma_gemm<2, 384>, cudaFuncAttributeMaxDynamicSharedMemorySize, GEMM_SMEM);
    cudaFuncSetAttribute(mma_gemm<3, 1536>, cudaFuncAttributeMaxDynamicSharedMemorySize, GEMM_SMEM);

    wconv<0><<<dim3(768 / 32, 384 / 32), dim3(32, 8)>>>(kvw, 384, 768);
    wconv<1><<<dim3(384 / 32, 384 / 32), dim3(32, 8)>>>(pw, 384, 384);
    wconv<2><<<dim3(1536 / 32, 384 / 32), dim3(32, 8)>>>(w1, 384, 1536);
    wconv<3><<<dim3(384 / 32, 1536 / 32), dim3(32, 8)>>>(w2, 1536, 384);

    ln1_kernel<<<LTOT, 128>>>(skip, xup, ln1g, ln1b);
    mma_gemm<0, 384><<<dim3(6, 172), 256, GEMM_SMEM>>>(kvb, nullptr, nullptr, nullptr, LTOT);
    attn_kernel<<<dim3(NWIN, NHEAD), ATHREADS, ATTN_SMEM>>>(rpb);
    mma_gemm<1, 384><<<dim3(3, 172), 256, GEMM_SMEM>>>(pb, skip, xup, nullptr, LTOT);
    ln2_kernel<<<LTOT, 128>>>(ln2g, ln2b);
    mma_gemm<2, 384><<<dim3(12, 172), 256, GEMM_SMEM>>>(b1, nullptr, nullptr, nullptr, LTOT);
    mma_gemm<3, 1536><<<dim3(3, 172), 256, GEMM_SMEM>>>(b2, nullptr, nullptr, out, LTOT);
}

// round 14
// speedup vs baseline: 2.7560x; 1.2988x over previous
#include <cuda_runtime.h>
#include <cuda_bf16.h>
#include <cuda_fp16.h>
#include <cstdint>
#include <math.h>

// Problem constants (B=1, D=H=W=28, C=384, NH=12, WS=7)
#define LTOT  21952
#define CH    384
#define NWIN  64
#define NTOK  343
#define NHEAD 12
#define HD    32
#define KPAD  345

// ---------------- scratch ----------------
__device__ float g_ln_q[LTOT * CH];
__device__ __half g_lnskip[LTOT * CH];
__device__ float g_kv[LTOT * 2 * CH];
__device__ __half g_o[LTOT * CH];
__device__ float g_x[LTOT * CH];
__device__ __half g_ln2[LTOT * CH];
__device__ __half g_h1[LTOT * 4 * CH];
__device__ __half g_wkv[768 * 384];
__device__ __half g_wp[384 * 384];
__device__ __half g_w1[1536 * 384];
__device__ __half g_w2[384 * 1536];

__device__ __forceinline__ int l_to_winrow(int l) {
    int d = l / 784, rem = l % 784, h = rem / 28, w = rem % 28;
    int win = (d / 7) * 16 + (h / 7) * 4 + (w / 7);
    int p = (d % 7) * 49 + (h % 7) * 7 + (w % 7);
    return win * NTOK + p;
}
__device__ __forceinline__ int winrow_to_l(int r) {
    int win = r / NTOK, p = r % NTOK;
    int wd = win >> 4, wh = (win >> 2) & 3, ww = win & 3;
    int pd = p / 49, ph = (p / 7) % 7, pw = p % 7;
    return (wd * 7 + pd) * 784 + (wh * 7 + ph) * 28 + (ww * 7 + pw);
}

// ---------------- mma.sync helpers ----------------
__device__ __forceinline__ uint32_t smem_u32(const void* p) {
    uint32_t a;
    asm("{ .reg .u64 t; cvta.to.shared.u64 t, %1; cvt.u32.u64 %0, t; }" : "=r"(a) : "l"(p));
    return a;
}
__device__ __forceinline__ void ldsm_x4(uint32_t* r, uint32_t addr) {
    asm volatile("ldmatrix.sync.aligned.m8n8.x4.shared.b16 {%0,%1,%2,%3}, [%4];"
                 : "=r"(r[0]), "=r"(r[1]), "=r"(r[2]), "=r"(r[3]) : "r"(addr));
}
__device__ __forceinline__ void ldsm_x2(uint32_t* r, uint32_t addr) {
    asm volatile("ldmatrix.sync.aligned.m8n8.x2.shared.b16 {%0,%1}, [%2];"
                 : "=r"(r[0]), "=r"(r[1]) : "r"(addr));
}
__device__ __forceinline__ void mma_f16(float* d, const uint32_t* a, const uint32_t* b) {
    asm volatile(
        "mma.sync.aligned.m16n8k16.row.col.f32.f16.f16.f32 "
        "{%0,%1,%2,%3}, {%4,%5,%6,%7}, {%8,%9}, {%0,%1,%2,%3};"
        : "+f"(d[0]), "+f"(d[1]), "+f"(d[2]), "+f"(d[3])
        : "r"(a[0]), "r"(a[1]), "r"(a[2]), "r"(a[3]), "r"(b[0]), "r"(b[1]));
}
__device__ __forceinline__ void cp_async16(uint32_t dst, const void* src, int pbytes) {
    asm volatile("cp.async.cg.shared.global [%0], [%1], 16, %2;"
                 :: "r"(dst), "l"(src), "r"(pbytes) : "memory");
}

// ---------------- weight transpose + fp16 convert: T[n][k] = W[k][n] -------
template <int WID>
__global__ void wconv(const float* __restrict__ W, int K, int N) {
    __half* T = (WID == 0) ? g_wkv : (WID == 1) ? g_wp : (WID == 2) ? g_w1 : g_w2;
    __shared__ float t[32][33];
    int nb = blockIdx.x * 32, kb = blockIdx.y * 32;
    int tx = threadIdx.x, ty = threadIdx.y;
#pragma unroll
    for (int i = 0; i < 4; i++) {
        int k = ty + i * 8;
        t[k][tx] = W[(size_t)(kb + k) * N + nb + tx];
    }
    __syncthreads();
#pragma unroll
    for (int i = 0; i < 4; i++) {
        int nrow = ty + i * 8;
        T[(size_t)(nb + nrow) * K + kb + tx] = __float2half_rn(t[tx][nrow]);
    }
}

// ---------------- LN1 ----------------
__global__ void ln1_kernel(const float* __restrict__ skip, const float* __restrict__ xup,
                           const float* __restrict__ g, const float* __restrict__ b) {
    int l = blockIdx.x;
    int tid = threadIdx.x;
    __shared__ float red[16];
    const float* sp = skip + (size_t)l * CH;
    const float* xp = xup + (size_t)l * CH;
    float v1[3], v2[3];
    float s1 = 0.f, q1 = 0.f, s2 = 0.f, q2 = 0.f;
#pragma unroll
    for (int i = 0; i < 3; i++) {
        int c = tid + i * 128;
        v1[i] = sp[c]; v2[i] = xp[c];
        s1 += v1[i]; q1 += v1[i] * v1[i];
        s2 += v2[i]; q2 += v2[i] * v2[i];
    }
#pragma unroll
    for (int o = 16; o > 0; o >>= 1) {
        s1 += __shfl_xor_sync(0xffffffffu, s1, o);
        q1 += __shfl_xor_sync(0xffffffffu, q1, o);
        s2 += __shfl_xor_sync(0xffffffffu, s2, o);
        q2 += __shfl_xor_sync(0xffffffffu, q2, o);
    }
    int wid = tid >> 5;
    if ((tid & 31) == 0) { red[wid] = s1; red[wid + 4] = q1; red[wid + 8] = s2; red[wid + 12] = q2; }
    __syncthreads();
    s1 = red[0] + red[1] + red[2] + red[3];
    q1 = red[4] + red[5] + red[6] + red[7];
    s2 = red[8] + red[9] + red[10] + red[11];
    q2 = red[12] + red[13] + red[14] + red[15];
    const float invC = 1.0f / CH;
    float m1 = s1 * invC, m2 = s2 * invC;
    float r1 = rsqrtf(q1 * invC - m1 * m1 + 1e-5f);
    float r2 = rsqrtf(q2 * invC - m2 * m2 + 1e-5f);
    int r = l_to_winrow(l);
    // hd^-0.5 * log2(e): scores produced directly in log2 domain
    const float QS = 0.25504626814056f;
#pragma unroll
    for (int i = 0; i < 3; i++) {
        int c = tid + i * 128;
        float gg = g[c], bb = b[c];
        float o1 = (v1[i] - m1) * r1 * gg + bb;
        size_t idx = (size_t)r * CH + c;
        g_lnskip[idx] = __float2half_rn(o1);
        g_ln_q[idx] = ((v2[i] - m2) * r2 * gg + bb) * QS;
    }
}

// ---------------- LN2 ----------------
__global__ void ln2_kernel(const float* __restrict__ g, const float* __restrict__ b) {
    int l = blockIdx.x;
    int tid = threadIdx.x;
    __shared__ float red[8];
    const float* xp = g_x + (size_t)l * CH;
    float v[3];
    float s = 0.f, q = 0.f;
#pragma unroll
    for (int i = 0; i < 3; i++) {
        v[i] = xp[tid + i * 128];
        s += v[i]; q += v[i] * v[i];
    }
#pragma unroll
    for (int o = 16; o > 0; o >>= 1) {
        s += __shfl_xor_sync(0xffffffffu, s, o);
        q += __shfl_xor_sync(0xffffffffu, q, o);
    }
    int wid = tid >> 5;
    if ((tid & 31) == 0) { red[wid] = s; red[wid + 4] = q; }
    __syncthreads();
    s = red[0] + red[1] + red[2] + red[3];
    q = red[4] + red[5] + red[6] + red[7];
    const float invC = 1.0f / CH;
    float m = s * invC;
    float rs = rsqrtf(q * invC - m * m + 1e-5f);
#pragma unroll
    for (int i = 0; i < 3; i++) {
        int c = tid + i * 128;
        float o = (v[i] - m) * rs * g[c] + b[c];
        g_ln2[(size_t)l * CH + c] = __float2half_rn(o);
    }
}

// ------- fp16 warp-mma GEMM, cp.async double-buffered (128x128, KC=32) -----
#define KC 32
#define APAD 40
#define ARR_BYTES (128 * APAD * 2)         // 10240
#define STAGE_BYTES (2 * ARR_BYTES)        // 20480
#define GEMM_SMEM (2 * STAGE_BYTES)        // 40960

template <int EPI, int KT>
__global__ void __launch_bounds__(256, 1)
mma_gemm(const float* __restrict__ bias, const float* __restrict__ e1,
         const float* __restrict__ e2, float* __restrict__ out, int M) {
    const __half* A = (EPI == 0) ? g_lnskip : (EPI == 1) ? g_o : (EPI == 2) ? g_ln2 : g_h1;
    const __half* B = (EPI == 0) ? g_wkv : (EPI == 1) ? g_wp : (EPI == 2) ? g_w1 : g_w2;

    extern __shared__ __align__(16) char dsm[];
    uint32_t sb = smem_u32(dsm);

    int tid = threadIdx.x;
    int lane = tid & 31, wid = tid >> 5;
    int rowBase = blockIdx.y * 128;
    int n0 = blockIdx.x * 128;
    int wm = (wid >> 2) * 64, wn = (wid & 3) * 32;

    float acc[4][4][4];
#pragma unroll
    for (int a = 0; a < 4; a++)
#pragma unroll
        for (int b = 0; b < 4; b++)
#pragma unroll
            for (int c = 0; c < 4; c++) acc[a][b][c] = 0.f;

    int lrow0 = tid >> 2, lc0 = (tid & 3);
    int lrow1 = (tid + 256) >> 2, lc1 = (tid & 3);
    uint32_t so0 = (uint32_t)(lrow0 * APAD + lc0 * 8) * 2;
    uint32_t so1 = (uint32_t)(lrow1 * APAD + lc1 * 8) * 2;

    auto issue_chunk = [&](int ch, int stage) {
        int kb = ch * KC;
        uint32_t sbase = sb + stage * STAGE_BYTES;
        {
            int r = rowBase + lrow0;
            bool v = r < M;
            const __half* pa = A + ((size_t)(v ? r : 0) * KT + kb + lc0 * 8);
            cp_async16(sbase + so0, pa, v ? 16 : 0);
            const __half* pb = B + ((size_t)(n0 + lrow0) * KT + kb + lc0 * 8);
            cp_async16(sbase + ARR_BYTES + so0, pb, 16);
        }
        {
            int r = rowBase + lrow1;
            bool v = r < M;
            const __half* pa = A + ((size_t)(v ? r : 0) * KT + kb + lc1 * 8);
            cp_async16(sbase + so1, pa, v ? 16 : 0);
            const __half* pb = B + ((size_t)(n0 + lrow1) * KT + kb + lc1 * 8);
            cp_async16(sbase + ARR_BYTES + so1, pb, 16);
        }
        asm volatile("cp.async.commit_group;" ::: "memory");
    };

    int aoffA = (lane & 15) * APAD + (lane >> 4) * 8;
    int aoffB = (lane & 7) * APAD + ((lane >> 3) & 1) * 8;

    const int NCH = KT / KC;
    issue_chunk(0, 0);
    for (int ch = 0; ch < NCH; ch++) {
        int cur = ch & 1;
        if (ch + 1 < NCH) {
            issue_chunk(ch + 1, cur ^ 1);
            asm volatile("cp.async.wait_group 1;" ::: "memory");
        } else {
            asm volatile("cp.async.wait_group 0;" ::: "memory");
        }
        __syncthreads();
        uint32_t aA = sb + cur * STAGE_BYTES;
        uint32_t aB = aA + ARR_BYTES;
#pragma unroll
        for (int s = 0; s < 2; s++) {
            int k0 = s * 16;
            uint32_t ah[4][4], bh[4][2];
#pragma unroll
            for (int mf = 0; mf < 4; mf++) {
                uint32_t off = ((wm + mf * 16) * APAD + k0 + aoffA) * 2;
                ldsm_x4(ah[mf], aA + off);
            }
#pragma unroll
            for (int nf = 0; nf < 4; nf++) {
                uint32_t off = ((wn + nf * 8) * APAD + k0 + aoffB) * 2;
                ldsm_x2(bh[nf], aB + off);
            }
#pragma unroll
            for (int mf = 0; mf < 4; mf++)
#pragma unroll
                for (int nf = 0; nf < 4; nf++)
                    mma_f16(acc[mf][nf], ah[mf], bh[nf]);
        }
        __syncthreads();
    }

    int lane4 = lane >> 2, lanec = (lane & 3) * 2;
#pragma unroll
    for (int mf = 0; mf < 4; mf++) {
#pragma unroll
        for (int half = 0; half < 2; half++) {
            int row = rowBase + wm + mf * 16 + lane4 + half * 8;
            if (row >= M) continue;
            int l = 0;
            if (EPI == 1) l = winrow_to_l(row);
#pragma unroll
            for (int nf = 0; nf < 4; nf++) {
#pragma unroll
                for (int e = 0; e < 2; e++) {
                    int col = n0 + wn + nf * 8 + lanec + e;
                    float v = acc[mf][nf][half * 2 + e] + bias[col];
                    if (EPI == 0) {
                        g_kv[(size_t)row * 768 + col] = v;
                    } else if (EPI == 1) {
                        size_t idx = (size_t)l * CH + col;
                        g_x[idx] = e1[idx] + e2[idx] + v;
                    } else if (EPI == 2) {
                        float t = tanhf(0.7978845608028654f * (v + 0.044715f * v * v * v));
                        float gv = 0.5f * v * (1.0f + t);
                        g_h1[(size_t)row * 1536 + col] = __float2half_rn(gv);
                    } else {
                        size_t idx = (size_t)row * CH + col;
                        out[idx] = g_x[idx] + v;
                    }
                }
            }
        }
    }
}

// --- fused window attention (R=2, log2 scores, f16x2 exp2, HFMA2 PV) -------
#define ATHREADS 512
#define NWARP 16
#define JPAD 352  // padded j-extent (22*16) for guard-free PV
// floats: q 10976 + k 11040 + bias 2198 ; halves: vh 352*32 ; half2: pw 16*352
#define ATTN_SMEM ((10976 + 11040 + 2198) * 4 + JPAD * 32 * 2 + NWARP * JPAD * 4)

__global__ void __launch_bounds__(ATHREADS) attn_kernel(const float* __restrict__ rpb) {
    int win = blockIdx.x, head = blockIdx.y;
    extern __shared__ float sm[];
    float* q_s = sm;
    float* k_s = q_s + 10976;
    float* bias_s = k_s + 11040;
    __half* vh_s = (__half*)(bias_s + 2198);          // [JPAD][32]
    __half2* pall = (__half2*)(vh_s + JPAD * 32);     // NWARP x JPAD
    int tid = threadIdx.x;
    const size_t base = (size_t)win * NTOK;
    const float LOG2E = 1.4426950408889634f;
    for (int idx = tid; idx < NTOK * HD; idx += ATHREADS) {
        int j = idx >> 5, d = idx & 31;
        q_s[idx] = g_ln_q[(base + j) * CH + head * HD + d];
        k_s[d * KPAD + j] = g_kv[(base + j) * 768 + head * HD + d];
    }
    for (int idx = tid; idx < JPAD * HD; idx += ATHREADS) {
        int j = idx >> 5, d = idx & 31;
        vh_s[idx] = (j < NTOK) ? __float2half_rn(g_kv[(base + j) * 768 + 384 + head * HD + d])
                               : __float2half_rn(0.f);
    }
    for (int idx = tid; idx < 2197; idx += ATHREADS)
        bias_s[idx] = rpb[idx * NHEAD + head] * LOG2E;
    __syncthreads();

    int lane = tid & 31, wid = tid >> 5;
    __half2* pw = pall + wid * JPAD;
    // zero the pad probs once (never rewritten: main loop writes only j < NTOK)
    if (lane < JPAD - NTOK) pw[NTOK + lane] = __float2half2_rn(0.f);

    for (int rp = wid; rp < 172; rp += NWARP) {
        int r0 = rp * 2, r1 = rp * 2 + 1;
        bool has1 = r1 < NTOK;
        int r1c = has1 ? r1 : r0;
        float qa[32], qb[32];
#pragma unroll
        for (int i = 0; i < 8; i++) {
            float4 t0 = *(const float4*)(q_s + r0 * 32 + i * 4);
            float4 t1 = *(const float4*)(q_s + r1c * 32 + i * 4);
            qa[i * 4 + 0] = t0.x; qa[i * 4 + 1] = t0.y; qa[i * 4 + 2] = t0.z; qa[i * 4 + 3] = t0.w;
            qb[i * 4 + 0] = t1.x; qb[i * 4 + 1] = t1.y; qb[i * 4 + 2] = t1.z; qb[i * 4 + 3] = t1.w;
        }
        int pd0 = r0 / 49, ph0 = (r0 / 7) % 7, pw0 = r0 % 7;
        int pd1 = r1c / 49, ph1 = (r1c / 7) % 7, pw1 = r1c % 7;
        float sv0[11], sv1[11];
        float m0 = -1e30f, m1 = -1e30f;
#pragma unroll
        for (int t = 0; t < 11; t++) {
            int j = lane + t * 32;
            if (j < NTOK) {
                int kd = j / 49, kh = (j / 7) % 7, kw = j % 7;
                int bo = (6 - kd) * 169 + (6 - kh) * 13 + (6 - kw);
                float s0 = bias_s[pd0 * 169 + ph0 * 13 + pw0 + bo];
                float s1 = bias_s[pd1 * 169 + ph1 * 13 + pw1 + bo];
#pragma unroll
                for (int d = 0; d < 32; d++) {
                    float kk = k_s[d * KPAD + j];
                    s0 += qa[d] * kk;
                    s1 += qb[d] * kk;
                }
                sv0[t] = s0; sv1[t] = s1;
                m0 = fmaxf(m0, s0); m1 = fmaxf(m1, s1);
            } else { sv0[t] = -1e30f; sv1[t] = -1e30f; }
        }
#pragma unroll
        for (int o = 16; o > 0; o >>= 1) {
            m0 = fmaxf(m0, __shfl_xor_sync(0xffffffffu, m0, o));
            m1 = fmaxf(m1, __shfl_xor_sync(0xffffffffu, m1, o));
        }
        float sum0 = 0.f, sum1 = 0.f;
#pragma unroll
        for (int t = 0; t < 11; t++) {
            int j = lane + t * 32;
            if (j < NTOK) {
                __half2 hx = __floats2half2_rn(sv0[t] - m0, sv1[t] - m1);
                __half2 hp = h2exp2(hx);
                pw[j] = hp;
                float2 f = __half22float2(hp);
                sum0 += f.x; sum1 += f.y;
            }
        }
#pragma unroll
        for (int o = 16; o > 0; o >>= 1) {
            sum0 += __shfl_xor_sync(0xffffffffu, sum0, o);
            sum1 += __shfl_xor_sync(0xffffffffu, sum1, o);
        }
        float inv0 = 1.0f / sum0, inv1 = 1.0f / sum1;
        __syncwarp();
        // PV: half2 HFMA2, chunked fp16 accumulation flushed to fp32 every 16 j
        float a0 = 0.f, a1 = 0.f;
        for (int c = 0; c < JPAD / 16; c++) {
            __half2 acc = __float2half2_rn(0.f);
#pragma unroll
            for (int u = 0; u < 16; u++) {
                int j = c * 16 + u;
                __half2 p01 = pw[j];
                __half2 vd = __half2half2(vh_s[j * 32 + lane]);
                acc = __hfma2(p01, vd, acc);
            }
            float2 f = __half22float2(acc);
            a0 += f.x; a1 += f.y;
        }
        g_o[(base + r0) * CH + head * HD + lane] = __float2half_rn(a0 * inv0);
        if (has1)
            g_o[(base + r1) * CH + head * HD + lane] = __float2half_rn(a1 * inv1);
        __syncwarp();
    }
}

// ---------------- launch ----------------
extern "C" void kernel_launch(void* const* d_in, const int* in_sizes, int n_in,
                              void* d_out, int out_size) {
    const float* skip = (const float*)d_in[0];
    const float* xup  = (const float*)d_in[1];
    const float* ln1g = (const float*)d_in[5];
    const float* ln1b = (const float*)d_in[6];
    const float* kvw  = (const float*)d_in[7];
    const float* kvb  = (const float*)d_in[8];
    const float* rpb  = (const float*)d_in[9];
    const float* pw   = (const float*)d_in[10];
    const float* pb   = (const float*)d_in[11];
    const float* ln2g = (const float*)d_in[12];
    const float* ln2b = (const float*)d_in[13];
    const float* w1   = (const float*)d_in[14];
    const float* b1   = (const float*)d_in[15];
    const float* w2   = (const float*)d_in[16];
    const float* b2   = (const float*)d_in[17];
    float* out = (float*)d_out;

    cudaFuncSetAttribute(attn_kernel, cudaFuncAttributeMaxDynamicSharedMemorySize, ATTN_SMEM);
    cudaFuncSetAttribute(mma_gemm<0, 384>, cudaFuncAttributeMaxDynamicSharedMemorySize, GEMM_SMEM);
    cudaFuncSetAttribute(mma_gemm<1, 384>, cudaFuncAttributeMaxDynamicSharedMemorySize, GEMM_SMEM);
    cudaFuncSetAttribute(mma_gemm<2, 384>, cudaFuncAttributeMaxDynamicSharedMemorySize, GEMM_SMEM);
    cudaFuncSetAttribute(mma_gemm<3, 1536>, cudaFuncAttributeMaxDynamicSharedMemorySize, GEMM_SMEM);

    wconv<0><<<dim3(768 / 32, 384 / 32), dim3(32, 8)>>>(kvw, 384, 768);
    wconv<1><<<dim3(384 / 32, 384 / 32), dim3(32, 8)>>>(pw, 384, 384);
    wconv<2><<<dim3(1536 / 32, 384 / 32), dim3(32, 8)>>>(w1, 384, 1536);
    wconv<3><<<dim3(384 / 32, 1536 / 32), dim3(32, 8)>>>(w2, 1536, 384);

    ln1_kernel<<<LTOT, 128>>>(skip, xup, ln1g, ln1b);
    mma_gemm<0, 384><<<dim3(6, 172), 256, GEMM_SMEM>>>(kvb, nullptr, nullptr, nullptr, LTOT);
    attn_kernel<<<dim3(NWIN, NHEAD), ATHREADS, ATTN_SMEM>>>(rpb);
    mma_gemm<1, 384><<<dim3(3, 172), 256, GEMM_SMEM>>>(pb, skip, xup, nullptr, LTOT);
    ln2_kernel<<<LTOT, 128>>>(ln2g, ln2b);
    mma_gemm<2, 384><<<dim3(12, 172), 256, GEMM_SMEM>>>(b1, nullptr, nullptr, nullptr, LTOT);
    mma_gemm<3, 1536><<<dim3(3, 172), 256, GEMM_SMEM>>>(b2, nullptr, nullptr, out, LTOT);
}

// round 15
// speedup vs baseline: 2.9477x; 1.0695x over previous
#include <cuda_runtime.h>
#include <cuda_bf16.h>
#include <cuda_fp16.h>
#include <cstdint>
#include <math.h>

// Problem constants (B=1, D=H=W=28, C=384, NH=12, WS=7)
#define LTOT  21952
#define CH    384
#define NWIN  64
#define NTOK  343
#define NHEAD 12
#define HD    32
#define KPAD  345

// ---------------- scratch ----------------
__device__ float g_ln_q[LTOT * CH];
__device__ __half g_lnskip[LTOT * CH];
__device__ float g_kv[LTOT * 2 * CH];
__device__ __half g_o[LTOT * CH];
__device__ float g_x[LTOT * CH];
__device__ __half g_ln2[LTOT * CH];
__device__ __half g_h1[LTOT * 4 * CH];
__device__ __half g_wkv[768 * 384];
__device__ __half g_wp[384 * 384];
__device__ __half g_w1[1536 * 384];
__device__ __half g_w2[384 * 1536];

__device__ __forceinline__ int l_to_winrow(int l) {
    int d = l / 784, rem = l % 784, h = rem / 28, w = rem % 28;
    int win = (d / 7) * 16 + (h / 7) * 4 + (w / 7);
    int p = (d % 7) * 49 + (h % 7) * 7 + (w % 7);
    return win * NTOK + p;
}
__device__ __forceinline__ int winrow_to_l(int r) {
    int win = r / NTOK, p = r % NTOK;
    int wd = win >> 4, wh = (win >> 2) & 3, ww = win & 3;
    int pd = p / 49, ph = (p / 7) % 7, pw = p % 7;
    return (wd * 7 + pd) * 784 + (wh * 7 + ph) * 28 + (ww * 7 + pw);
}

// ---------------- mma.sync helpers ----------------
__device__ __forceinline__ uint32_t smem_u32(const void* p) {
    uint32_t a;
    asm("{ .reg .u64 t; cvta.to.shared.u64 t, %1; cvt.u32.u64 %0, t; }" : "=r"(a) : "l"(p));
    return a;
}
__device__ __forceinline__ void ldsm_x4(uint32_t* r, uint32_t addr) {
    asm volatile("ldmatrix.sync.aligned.m8n8.x4.shared.b16 {%0,%1,%2,%3}, [%4];"
                 : "=r"(r[0]), "=r"(r[1]), "=r"(r[2]), "=r"(r[3]) : "r"(addr));
}
__device__ __forceinline__ void ldsm_x2(uint32_t* r, uint32_t addr) {
    asm volatile("ldmatrix.sync.aligned.m8n8.x2.shared.b16 {%0,%1}, [%2];"
                 : "=r"(r[0]), "=r"(r[1]) : "r"(addr));
}
__device__ __forceinline__ void mma_f16(float* d, const uint32_t* a, const uint32_t* b) {
    asm volatile(
        "mma.sync.aligned.m16n8k16.row.col.f32.f16.f16.f32 "
        "{%0,%1,%2,%3}, {%4,%5,%6,%7}, {%8,%9}, {%0,%1,%2,%3};"
        : "+f"(d[0]), "+f"(d[1]), "+f"(d[2]), "+f"(d[3])
        : "r"(a[0]), "r"(a[1]), "r"(a[2]), "r"(a[3]), "r"(b[0]), "r"(b[1]));
}
__device__ __forceinline__ void cp_async16(uint32_t dst, const void* src, int pbytes) {
    asm volatile("cp.async.cg.shared.global [%0], [%1], 16, %2;"
                 :: "r"(dst), "l"(src), "r"(pbytes) : "memory");
}

// ---------------- weight transpose + fp16 convert: T[n][k] = W[k][n] -------
template <int WID>
__global__ void wconv(const float* __restrict__ W, int K, int N) {
    __half* T = (WID == 0) ? g_wkv : (WID == 1) ? g_wp : (WID == 2) ? g_w1 : g_w2;
    __shared__ float t[32][33];
    int nb = blockIdx.x * 32, kb = blockIdx.y * 32;
    int tx = threadIdx.x, ty = threadIdx.y;
#pragma unroll
    for (int i = 0; i < 4; i++) {
        int k = ty + i * 8;
        t[k][tx] = W[(size_t)(kb + k) * N + nb + tx];
    }
    __syncthreads();
#pragma unroll
    for (int i = 0; i < 4; i++) {
        int nrow = ty + i * 8;
        T[(size_t)(nb + nrow) * K + kb + tx] = __float2half_rn(t[tx][nrow]);
    }
}

// ---------------- LN1 ----------------
__global__ void ln1_kernel(const float* __restrict__ skip, const float* __restrict__ xup,
                           const float* __restrict__ g, const float* __restrict__ b) {
    int l = blockIdx.x;
    int tid = threadIdx.x;
    __shared__ float red[16];
    const float* sp = skip + (size_t)l * CH;
    const float* xp = xup + (size_t)l * CH;
    float v1[3], v2[3];
    float s1 = 0.f, q1 = 0.f, s2 = 0.f, q2 = 0.f;
#pragma unroll
    for (int i = 0; i < 3; i++) {
        int c = tid + i * 128;
        v1[i] = sp[c]; v2[i] = xp[c];
        s1 += v1[i]; q1 += v1[i] * v1[i];
        s2 += v2[i]; q2 += v2[i] * v2[i];
    }
#pragma unroll
    for (int o = 16; o > 0; o >>= 1) {
        s1 += __shfl_xor_sync(0xffffffffu, s1, o);
        q1 += __shfl_xor_sync(0xffffffffu, q1, o);
        s2 += __shfl_xor_sync(0xffffffffu, s2, o);
        q2 += __shfl_xor_sync(0xffffffffu, q2, o);
    }
    int wid = tid >> 5;
    if ((tid & 31) == 0) { red[wid] = s1; red[wid + 4] = q1; red[wid + 8] = s2; red[wid + 12] = q2; }
    __syncthreads();
    s1 = red[0] + red[1] + red[2] + red[3];
    q1 = red[4] + red[5] + red[6] + red[7];
    s2 = red[8] + red[9] + red[10] + red[11];
    q2 = red[12] + red[13] + red[14] + red[15];
    const float invC = 1.0f / CH;
    float m1 = s1 * invC, m2 = s2 * invC;
    float r1 = rsqrtf(q1 * invC - m1 * m1 + 1e-5f);
    float r2 = rsqrtf(q2 * invC - m2 * m2 + 1e-5f);
    int r = l_to_winrow(l);
    // hd^-0.5 * log2(e): scores produced directly in log2 domain
    const float QS = 0.25504626814056f;
#pragma unroll
    for (int i = 0; i < 3; i++) {
        int c = tid + i * 128;
        float gg = g[c], bb = b[c];
        float o1 = (v1[i] - m1) * r1 * gg + bb;
        size_t idx = (size_t)r * CH + c;
        g_lnskip[idx] = __float2half_rn(o1);
        g_ln_q[idx] = ((v2[i] - m2) * r2 * gg + bb) * QS;
    }
}

// ---------------- LN2 ----------------
__global__ void ln2_kernel(const float* __restrict__ g, const float* __restrict__ b) {
    int l = blockIdx.x;
    int tid = threadIdx.x;
    __shared__ float red[8];
    const float* xp = g_x + (size_t)l * CH;
    float v[3];
    float s = 0.f, q = 0.f;
#pragma unroll
    for (int i = 0; i < 3; i++) {
        v[i] = xp[tid + i * 128];
        s += v[i]; q += v[i] * v[i];
    }
#pragma unroll
    for (int o = 16; o > 0; o >>= 1) {
        s += __shfl_xor_sync(0xffffffffu, s, o);
        q += __shfl_xor_sync(0xffffffffu, q, o);
    }
    int wid = tid >> 5;
    if ((tid & 31) == 0) { red[wid] = s; red[wid + 4] = q; }
    __syncthreads();
    s = red[0] + red[1] + red[2] + red[3];
    q = red[4] + red[5] + red[6] + red[7];
    const float invC = 1.0f / CH;
    float m = s * invC;
    float rs = rsqrtf(q * invC - m * m + 1e-5f);
#pragma unroll
    for (int i = 0; i < 3; i++) {
        int c = tid + i * 128;
        float o = (v[i] - m) * rs * g[c] + b[c];
        g_ln2[(size_t)l * CH + c] = __float2half_rn(o);
    }
}

// ------- fp16 warp-mma GEMM, cp.async double-buffered (128x128, KC=32) -----
#define KC 32
#define APAD 40
#define ARR_BYTES (128 * APAD * 2)         // 10240
#define STAGE_BYTES (2 * ARR_BYTES)        // 20480
#define GEMM_SMEM (2 * STAGE_BYTES)        // 40960

template <int EPI, int KT>
__global__ void __launch_bounds__(256, 1)
mma_gemm(const float* __restrict__ bias, const float* __restrict__ e1,
         const float* __restrict__ e2, float* __restrict__ out, int M) {
    const __half* A = (EPI == 0) ? g_lnskip : (EPI == 1) ? g_o : (EPI == 2) ? g_ln2 : g_h1;
    const __half* B = (EPI == 0) ? g_wkv : (EPI == 1) ? g_wp : (EPI == 2) ? g_w1 : g_w2;

    extern __shared__ __align__(16) char dsm[];
    uint32_t sb = smem_u32(dsm);

    int tid = threadIdx.x;
    int lane = tid & 31, wid = tid >> 5;
    int rowBase = blockIdx.y * 128;
    int n0 = blockIdx.x * 128;
    int wm = (wid >> 2) * 64, wn = (wid & 3) * 32;

    float acc[4][4][4];
#pragma unroll
    for (int a = 0; a < 4; a++)
#pragma unroll
        for (int b = 0; b < 4; b++)
#pragma unroll
            for (int c = 0; c < 4; c++) acc[a][b][c] = 0.f;

    int lrow0 = tid >> 2, lc0 = (tid & 3);
    int lrow1 = (tid + 256) >> 2, lc1 = (tid & 3);
    uint32_t so0 = (uint32_t)(lrow0 * APAD + lc0 * 8) * 2;
    uint32_t so1 = (uint32_t)(lrow1 * APAD + lc1 * 8) * 2;

    auto issue_chunk = [&](int ch, int stage) {
        int kb = ch * KC;
        uint32_t sbase = sb + stage * STAGE_BYTES;
        {
            int r = rowBase + lrow0;
            bool v = r < M;
            const __half* pa = A + ((size_t)(v ? r : 0) * KT + kb + lc0 * 8);
            cp_async16(sbase + so0, pa, v ? 16 : 0);
            const __half* pb = B + ((size_t)(n0 + lrow0) * KT + kb + lc0 * 8);
            cp_async16(sbase + ARR_BYTES + so0, pb, 16);
        }
        {
            int r = rowBase + lrow1;
            bool v = r < M;
            const __half* pa = A + ((size_t)(v ? r : 0) * KT + kb + lc1 * 8);
            cp_async16(sbase + so1, pa, v ? 16 : 0);
            const __half* pb = B + ((size_t)(n0 + lrow1) * KT + kb + lc1 * 8);
            cp_async16(sbase + ARR_BYTES + so1, pb, 16);
        }
        asm volatile("cp.async.commit_group;" ::: "memory");
    };

    int aoffA = (lane & 15) * APAD + (lane >> 4) * 8;
    int aoffB = (lane & 7) * APAD + ((lane >> 3) & 1) * 8;

    const int NCH = KT / KC;
    issue_chunk(0, 0);
    for (int ch = 0; ch < NCH; ch++) {
        int cur = ch & 1;
        if (ch + 1 < NCH) {
            issue_chunk(ch + 1, cur ^ 1);
            asm volatile("cp.async.wait_group 1;" ::: "memory");
        } else {
            asm volatile("cp.async.wait_group 0;" ::: "memory");
        }
        __syncthreads();
        uint32_t aA = sb + cur * STAGE_BYTES;
        uint32_t aB = aA + ARR_BYTES;
#pragma unroll
        for (int s = 0; s < 2; s++) {
            int k0 = s * 16;
            uint32_t ah[4][4], bh[4][2];
#pragma unroll
            for (int mf = 0; mf < 4; mf++) {
                uint32_t off = ((wm + mf * 16) * APAD + k0 + aoffA) * 2;
                ldsm_x4(ah[mf], aA + off);
            }
#pragma unroll
            for (int nf = 0; nf < 4; nf++) {
                uint32_t off = ((wn + nf * 8) * APAD + k0 + aoffB) * 2;
                ldsm_x2(bh[nf], aB + off);
            }
#pragma unroll
            for (int mf = 0; mf < 4; mf++)
#pragma unroll
                for (int nf = 0; nf < 4; nf++)
                    mma_f16(acc[mf][nf], ah[mf], bh[nf]);
        }
        __syncthreads();
    }

    int lane4 = lane >> 2, lanec = (lane & 3) * 2;
#pragma unroll
    for (int mf = 0; mf < 4; mf++) {
#pragma unroll
        for (int half = 0; half < 2; half++) {
            int row = rowBase + wm + mf * 16 + lane4 + half * 8;
            if (row >= M) continue;
            int l = 0;
            if (EPI == 1) l = winrow_to_l(row);
#pragma unroll
            for (int nf = 0; nf < 4; nf++) {
#pragma unroll
                for (int e = 0; e < 2; e++) {
                    int col = n0 + wn + nf * 8 + lanec + e;
                    float v = acc[mf][nf][half * 2 + e] + bias[col];
                    if (EPI == 0) {
                        g_kv[(size_t)row * 768 + col] = v;
                    } else if (EPI == 1) {
                        size_t idx = (size_t)l * CH + col;
                        g_x[idx] = e1[idx] + e2[idx] + v;
                    } else if (EPI == 2) {
                        float t = tanhf(0.7978845608028654f * (v + 0.044715f * v * v * v));
                        float gv = 0.5f * v * (1.0f + t);
                        g_h1[(size_t)row * 1536 + col] = __float2half_rn(gv);
                    } else {
                        size_t idx = (size_t)row * CH + col;
                        out[idx] = g_x[idx] + v;
                    }
                }
            }
        }
    }
}

// --- fused window attention: R=2, log2 scores, f16x2 exp2, packed k/v ------
// k packed as half2 over d-pairs; v packed as half2 over j-pairs.
#define ATHREADS 512
#define NWARP 16
#define JPAD 352                 // padded j extent (176 j-pairs)
#define NJP (JPAD / 2)           // 176
// floats: q 10976 + bias 2198 ; half2: k2 16*345, vh2 176*32, pw 16*352
#define ATTN_SMEM ((10976 + 2198) * 4 + 16 * KPAD * 4 + NJP * 32 * 4 + NWARP * JPAD * 4)

__global__ void __launch_bounds__(ATHREADS) attn_kernel(const float* __restrict__ rpb) {
    int win = blockIdx.x, head = blockIdx.y;
    extern __shared__ float sm[];
    float* q_s = sm;                                   // [343][32] fp32
    float* bias_s = q_s + 10976;                       // [2197]
    __half2* k2_s = (__half2*)(bias_s + 2198);         // [16][KPAD] d-pairs
    __half2* vh2_s = k2_s + 16 * KPAD;                 // [176][32] j-pairs
    __half2* pall = vh2_s + NJP * 32;                  // NWARP x JPAD
    int tid = threadIdx.x;
    const size_t base = (size_t)win * NTOK;
    const float LOG2E = 1.4426950408889634f;
    // q (fp32) loader
    for (int idx = tid; idx < NTOK * HD; idx += ATHREADS) {
        int j = idx >> 5, d = idx & 31;
        q_s[idx] = g_ln_q[(base + j) * CH + head * HD + d];
    }
    // k2 loader: k2_s[dp][j] = (k[2dp][j], k[2dp+1][j])
    for (int idx = tid; idx < NTOK * 16; idx += ATHREADS) {
        int j = idx >> 4, dp = idx & 15;
        const float2* kv2 = (const float2*)(g_kv + (base + j) * 768 + head * HD);
        float2 kk = kv2[dp];
        k2_s[dp * KPAD + j] = __floats2half2_rn(kk.x, kk.y);
    }
    // vh2 loader: vh2_s[jp][d] = (v[2jp][d], v[2jp+1][d]), zero pad
    for (int idx = tid; idx < NJP * HD; idx += ATHREADS) {
        int jp = idx >> 5, d = idx & 31;
        int j0 = 2 * jp, j1 = 2 * jp + 1;
        float v0 = (j0 < NTOK) ? g_kv[(base + j0) * 768 + 384 + head * HD + d] : 0.f;
        float v1 = (j1 < NTOK) ? g_kv[(base + j1) * 768 + 384 + head * HD + d] : 0.f;
        vh2_s[idx] = __floats2half2_rn(v0, v1);
    }
    for (int idx = tid; idx < 2197; idx += ATHREADS)
        bias_s[idx] = rpb[idx * NHEAD + head] * LOG2E;
    __syncthreads();

    int lane = tid & 31, wid = tid >> 5;
    __half2* pw = pall + wid * JPAD;
    // zero pad probs once (main loop writes only j < NTOK)
    if (lane < JPAD - NTOK) pw[NTOK + lane] = __float2half2_rn(0.f);

    for (int rp = wid; rp < 172; rp += NWARP) {
        int r0 = rp * 2, r1 = rp * 2 + 1;
        bool has1 = r1 < NTOK;
        int r1c = has1 ? r1 : r0;
        float qa[32], qb[32];
#pragma unroll
        for (int i = 0; i < 8; i++) {
            float4 t0 = *(const float4*)(q_s + r0 * 32 + i * 4);
            float4 t1 = *(const float4*)(q_s + r1c * 32 + i * 4);
            qa[i * 4 + 0] = t0.x; qa[i * 4 + 1] = t0.y; qa[i * 4 + 2] = t0.z; qa[i * 4 + 3] = t0.w;
            qb[i * 4 + 0] = t1.x; qb[i * 4 + 1] = t1.y; qb[i * 4 + 2] = t1.z; qb[i * 4 + 3] = t1.w;
        }
        int pd0 = r0 / 49, ph0 = (r0 / 7) % 7, pw0 = r0 % 7;
        int pd1 = r1c / 49, ph1 = (r1c / 7) % 7, pw1 = r1c % 7;
        float sv0[11], sv1[11];
        float m0 = -1e30f, m1 = -1e30f;
#pragma unroll
        for (int t = 0; t < 11; t++) {
            int j = lane + t * 32;
            if (j < NTOK) {
                int kd = j / 49, kh = (j / 7) % 7, kw = j % 7;
                int bo = (6 - kd) * 169 + (6 - kh) * 13 + (6 - kw);
                float s0 = bias_s[pd0 * 169 + ph0 * 13 + pw0 + bo];
                float s1 = bias_s[pd1 * 169 + ph1 * 13 + pw1 + bo];
#pragma unroll
                for (int dp = 0; dp < 16; dp++) {
                    float2 kf = __half22float2(k2_s[dp * KPAD + j]);
                    s0 = fmaf(qa[2 * dp], kf.x, s0);
                    s0 = fmaf(qa[2 * dp + 1], kf.y, s0);
                    s1 = fmaf(qb[2 * dp], kf.x, s1);
                    s1 = fmaf(qb[2 * dp + 1], kf.y, s1);
                }
                sv0[t] = s0; sv1[t] = s1;
                m0 = fmaxf(m0, s0); m1 = fmaxf(m1, s1);
            } else { sv0[t] = -1e30f; sv1[t] = -1e30f; }
        }
#pragma unroll
        for (int o = 16; o > 0; o >>= 1) {
            m0 = fmaxf(m0, __shfl_xor_sync(0xffffffffu, m0, o));
            m1 = fmaxf(m1, __shfl_xor_sync(0xffffffffu, m1, o));
        }
        float sum0 = 0.f, sum1 = 0.f;
#pragma unroll
        for (int t = 0; t < 11; t++) {
            int j = lane + t * 32;
            if (j < NTOK) {
                __half2 hx = __floats2half2_rn(sv0[t] - m0, sv1[t] - m1);
                __half2 hp = h2exp2(hx);
                pw[j] = hp;
                float2 f = __half22float2(hp);
                sum0 += f.x; sum1 += f.y;
            }
        }
#pragma unroll
        for (int o = 16; o > 0; o >>= 1) {
            sum0 += __shfl_xor_sync(0xffffffffu, sum0, o);
            sum1 += __shfl_xor_sync(0xffffffffu, sum1, o);
        }
        float inv0 = 1.0f / sum0, inv1 = 1.0f / sum1;
        __syncwarp();
        // PV: per j-pair 1 v-LDS + 2 pw-LDS (broadcast); fp16 chunk accum,
        // flushed to fp32 every 8 j-pairs (16 j)
        float a0 = 0.f, a1 = 0.f;
        for (int c = 0; c < NJP / 8; c++) {
            __half2 acc = __float2half2_rn(0.f);
#pragma unroll
            for (int u = 0; u < 8; u++) {
                int jp = c * 8 + u;
                __half2 vv = vh2_s[jp * 32 + lane];
                acc = __hfma2(pw[2 * jp], __low2half2(vv), acc);
                acc = __hfma2(pw[2 * jp + 1], __high2half2(vv), acc);
            }
            float2 f = __half22float2(acc);
            a0 += f.x; a1 += f.y;
        }
        g_o[(base + r0) * CH + head * HD + lane] = __float2half_rn(a0 * inv0);
        if (has1)
            g_o[(base + r1) * CH + head * HD + lane] = __float2half_rn(a1 * inv1);
        __syncwarp();
    }
}

// ---------------- launch ----------------
extern "C" void kernel_launch(void* const* d_in, const int* in_sizes, int n_in,
                              void* d_out, int out_size) {
    const float* skip = (const float*)d_in[0];
    const float* xup  = (const float*)d_in[1];
    const float* ln1g = (const float*)d_in[5];
    const float* ln1b = (const float*)d_in[6];
    const float* kvw  = (const float*)d_in[7];
    const float* kvb  = (const float*)d_in[8];
    const float* rpb  = (const float*)d_in[9];
    const float* pw   = (const float*)d_in[10];
    const float* pb   = (const float*)d_in[11];
    const float* ln2g = (const float*)d_in[12];
    const float* ln2b = (const float*)d_in[13];
    const float* w1   = (const float*)d_in[14];
    const float* b1   = (const float*)d_in[15];
    const float* w2   = (const float*)d_in[16];
    const float* b2   = (const float*)d_in[17];
    float* out = (float*)d_out;

    cudaFuncSetAttribute(attn_kernel, cudaFuncAttributeMaxDynamicSharedMemorySize, ATTN_SMEM);
    cudaFuncSetAttribute(mma_gemm<0, 384>, cudaFuncAttributeMaxDynamicSharedMemorySize, GEMM_SMEM);
    cudaFuncSetAttribute(mma_gemm<1, 384>, cudaFuncAttributeMaxDynamicSharedMemorySize, GEMM_SMEM);
    cudaFuncSetAttribute(mma_gemm<2, 384>, cudaFuncAttributeMaxDynamicSharedMemorySize, GEMM_SMEM);
    cudaFuncSetAttribute(mma_gemm<3, 1536>, cudaFuncAttributeMaxDynamicSharedMemorySize, GEMM_SMEM);

    wconv<0><<<dim3(768 / 32, 384 / 32), dim3(32, 8)>>>(kvw, 384, 768);
    wconv<1><<<dim3(384 / 32, 384 / 32), dim3(32, 8)>>>(pw, 384, 384);
    wconv<2><<<dim3(1536 / 32, 384 / 32), dim3(32, 8)>>>(w1, 384, 1536);
    wconv<3><<<dim3(384 / 32, 1536 / 32), dim3(32, 8)>>>(w2, 1536, 384);

    ln1_kernel<<<LTOT, 128>>>(skip, xup, ln1g, ln1b);
    mma_gemm<0, 384><<<dim3(6, 172), 256, GEMM_SMEM>>>(kvb, nullptr, nullptr, nullptr, LTOT);
    attn_kernel<<<dim3(NWIN, NHEAD), ATHREADS, ATTN_SMEM>>>(rpb);
    mma_gemm<1, 384><<<dim3(3, 172), 256, GEMM_SMEM>>>(pb, skip, xup, nullptr, LTOT);
    ln2_kernel<<<LTOT, 128>>>(ln2g, ln2b);
    mma_gemm<2, 384><<<dim3(12, 172), 256, GEMM_SMEM>>>(b1, nullptr, nullptr, nullptr, LTOT);
    mma_gemm<3, 1536><<<dim3(3, 172), 256, GEMM_SMEM>>>(b2, nullptr, nullptr, out, LTOT);
}

// round 17
// speedup vs baseline: 3.3038x; 1.1208x over previous
#include <cuda_runtime.h>
#include <cuda_bf16.h>
#include <cuda_fp16.h>
#include <cstdint>
#include <math.h>

// Problem constants (B=1, D=H=W=28, C=384, NH=12, WS=7)
#define LTOT  21952
#define CH    384
#define NWIN  64
#define NTOK  343
#define NHEAD 12
#define HD    32
#define KPAD  345

// ---------------- scratch ----------------
__device__ __half g_lnq[LTOT * CH];
__device__ __half g_lnskip[LTOT * CH];
__device__ float g_kv[LTOT * 2 * CH];
__device__ __half g_o[LTOT * CH];
__device__ float g_x[LTOT * CH];
__device__ __half g_ln2[LTOT * CH];
__device__ __half g_h1[LTOT * 4 * CH];
__device__ __half g_wkv[768 * 384];
__device__ __half g_wp[384 * 384];
__device__ __half g_w1[1536 * 384];
__device__ __half g_w2[384 * 1536];

__device__ __forceinline__ int l_to_winrow(int l) {
    int d = l / 784, rem = l % 784, h = rem / 28, w = rem % 28;
    int win = (d / 7) * 16 + (h / 7) * 4 + (w / 7);
    int p = (d % 7) * 49 + (h % 7) * 7 + (w % 7);
    return win * NTOK + p;
}
__device__ __forceinline__ int winrow_to_l(int r) {
    int win = r / NTOK, p = r % NTOK;
    int wd = win >> 4, wh = (win >> 2) & 3, ww = win & 3;
    int pd = p / 49, ph = (p / 7) % 7, pw = p % 7;
    return (wd * 7 + pd) * 784 + (wh * 7 + ph) * 28 + (ww * 7 + pw);
}

// ---------------- mma.sync helpers ----------------
__device__ __forceinline__ uint32_t smem_u32(const void* p) {
    uint32_t a;
    asm("{ .reg .u64 t; cvta.to.shared.u64 t, %1; cvt.u32.u64 %0, t; }" : "=r"(a) : "l"(p));
    return a;
}
__device__ __forceinline__ void ldsm_x4(uint32_t* r, uint32_t addr) {
    asm volatile("ldmatrix.sync.aligned.m8n8.x4.shared.b16 {%0,%1,%2,%3}, [%4];"
                 : "=r"(r[0]), "=r"(r[1]), "=r"(r[2]), "=r"(r[3]) : "r"(addr));
}
__device__ __forceinline__ void ldsm_x2(uint32_t* r, uint32_t addr) {
    asm volatile("ldmatrix.sync.aligned.m8n8.x2.shared.b16 {%0,%1}, [%2];"
                 : "=r"(r[0]), "=r"(r[1]) : "r"(addr));
}
__device__ __forceinline__ void mma_f16(float* d, const uint32_t* a, const uint32_t* b) {
    asm volatile(
        "mma.sync.aligned.m16n8k16.row.col.f32.f16.f16.f32 "
        "{%0,%1,%2,%3}, {%4,%5,%6,%7}, {%8,%9}, {%0,%1,%2,%3};"
        : "+f"(d[0]), "+f"(d[1]), "+f"(d[2]), "+f"(d[3])
        : "r"(a[0]), "r"(a[1]), "r"(a[2]), "r"(a[3]), "r"(b[0]), "r"(b[1]));
}
__device__ __forceinline__ void cp_async16(uint32_t dst, const void* src, int pbytes) {
    asm volatile("cp.async.cg.shared.global [%0], [%1], 16, %2;"
                 :: "r"(dst), "l"(src), "r"(pbytes) : "memory");
}

// ---------------- weight transpose + fp16 convert: T[n][k] = W[k][n] -------
template <int WID>
__global__ void wconv(const float* __restrict__ W, int K, int N) {
    __half* T = (WID == 0) ? g_wkv : (WID == 1) ? g_wp : (WID == 2) ? g_w1 : g_w2;
    __shared__ float t[32][33];
    int nb = blockIdx.x * 32, kb = blockIdx.y * 32;
    int tx = threadIdx.x, ty = threadIdx.y;
#pragma unroll
    for (int i = 0; i < 4; i++) {
        int k = ty + i * 8;
        t[k][tx] = W[(size_t)(kb + k) * N + nb + tx];
    }
    __syncthreads();
#pragma unroll
    for (int i = 0; i < 4; i++) {
        int nrow = ty + i * 8;
        T[(size_t)(nb + nrow) * K + kb + tx] = __float2half_rn(t[tx][nrow]);
    }
}

// ---------------- LN1 ----------------
__global__ void ln1_kernel(const float* __restrict__ skip, const float* __restrict__ xup,
                           const float* __restrict__ g, const float* __restrict__ b) {
    int l = blockIdx.x;
    int tid = threadIdx.x;
    __shared__ float red[16];
    const float* sp = skip + (size_t)l * CH;
    const float* xp = xup + (size_t)l * CH;
    float v1[3], v2[3];
    float s1 = 0.f, q1 = 0.f, s2 = 0.f, q2 = 0.f;
#pragma unroll
    for (int i = 0; i < 3; i++) {
        int c = tid + i * 128;
        v1[i] = sp[c]; v2[i] = xp[c];
        s1 += v1[i]; q1 += v1[i] * v1[i];
        s2 += v2[i]; q2 += v2[i] * v2[i];
    }
#pragma unroll
    for (int o = 16; o > 0; o >>= 1) {
        s1 += __shfl_xor_sync(0xffffffffu, s1, o);
        q1 += __shfl_xor_sync(0xffffffffu, q1, o);
        s2 += __shfl_xor_sync(0xffffffffu, s2, o);
        q2 += __shfl_xor_sync(0xffffffffu, q2, o);
    }
    int wid = tid >> 5;
    if ((tid & 31) == 0) { red[wid] = s1; red[wid + 4] = q1; red[wid + 8] = s2; red[wid + 12] = q2; }
    __syncthreads();
    s1 = red[0] + red[1] + red[2] + red[3];
    q1 = red[4] + red[5] + red[6] + red[7];
    s2 = red[8] + red[9] + red[10] + red[11];
    q2 = red[12] + red[13] + red[14] + red[15];
    const float invC = 1.0f / CH;
    float m1 = s1 * invC, m2 = s2 * invC;
    float r1 = rsqrtf(q1 * invC - m1 * m1 + 1e-5f);
    float r2 = rsqrtf(q2 * invC - m2 * m2 + 1e-5f);
    int r = l_to_winrow(l);
    // hd^-0.5 * log2(e): scores produced directly in log2 domain
    const float QS = 0.25504626814056f;
#pragma unroll
    for (int i = 0; i < 3; i++) {
        int c = tid + i * 128;
        float gg = g[c], bb = b[c];
        float o1 = (v1[i] - m1) * r1 * gg + bb;
        size_t idx = (size_t)r * CH + c;
        g_lnskip[idx] = __float2half_rn(o1);
        g_lnq[idx] = __float2half_rn(((v2[i] - m2) * r2 * gg + bb) * QS);
    }
}

// ---------------- LN2 ----------------
__global__ void ln2_kernel(const float* __restrict__ g, const float* __restrict__ b) {
    int l = blockIdx.x;
    int tid = threadIdx.x;
    __shared__ float red[8];
    const float* xp = g_x + (size_t)l * CH;
    float v[3];
    float s = 0.f, q = 0.f;
#pragma unroll
    for (int i = 0; i < 3; i++) {
        v[i] = xp[tid + i * 128];
        s += v[i]; q += v[i] * v[i];
    }
#pragma unroll
    for (int o = 16; o > 0; o >>= 1) {
        s += __shfl_xor_sync(0xffffffffu, s, o);
        q += __shfl_xor_sync(0xffffffffu, q, o);
    }
    int wid = tid >> 5;
    if ((tid & 31) == 0) { red[wid] = s; red[wid + 4] = q; }
    __syncthreads();
    s = red[0] + red[1] + red[2] + red[3];
    q = red[4] + red[5] + red[6] + red[7];
    const float invC = 1.0f / CH;
    float m = s * invC;
    float rs = rsqrtf(q * invC - m * m + 1e-5f);
#pragma unroll
    for (int i = 0; i < 3; i++) {
        int c = tid + i * 128;
        float o = (v[i] - m) * rs * g[c] + b[c];
        g_ln2[(size_t)l * CH + c] = __float2half_rn(o);
    }
}

// ------- fp16 warp-mma GEMM, cp.async double-buffered (128x128, KC=32) -----
#define KC 32
#define APAD 40
#define ARR_BYTES (128 * APAD * 2)         // 10240
#define STAGE_BYTES (2 * ARR_BYTES)        // 20480
#define GEMM_SMEM (2 * STAGE_BYTES)        // 40960

template <int EPI, int KT>
__global__ void __launch_bounds__(256, 1)
mma_gemm(const float* __restrict__ bias, const float* __restrict__ e1,
         const float* __restrict__ e2, float* __restrict__ out, int M) {
    const __half* A = (EPI == 0) ? g_lnskip : (EPI == 1) ? g_o : (EPI == 2) ? g_ln2 : g_h1;
    const __half* B = (EPI == 0) ? g_wkv : (EPI == 1) ? g_wp : (EPI == 2) ? g_w1 : g_w2;

    extern __shared__ __align__(16) char dsm[];
    uint32_t sb = smem_u32(dsm);

    int tid = threadIdx.x;
    int lane = tid & 31, wid = tid >> 5;
    int rowBase = blockIdx.y * 128;
    int n0 = blockIdx.x * 128;
    int wm = (wid >> 2) * 64, wn = (wid & 3) * 32;

    float acc[4][4][4];
#pragma unroll
    for (int a = 0; a < 4; a++)
#pragma unroll
        for (int b = 0; b < 4; b++)
#pragma unroll
            for (int c = 0; c < 4; c++) acc[a][b][c] = 0.f;

    int lrow0 = tid >> 2, lc0 = (tid & 3);
    int lrow1 = (tid + 256) >> 2, lc1 = (tid & 3);
    uint32_t so0 = (uint32_t)(lrow0 * APAD + lc0 * 8) * 2;
    uint32_t so1 = (uint32_t)(lrow1 * APAD + lc1 * 8) * 2;

    auto issue_chunk = [&](int ch, int stage) {
        int kb = ch * KC;
        uint32_t sbase = sb + stage * STAGE_BYTES;
        {
            int r = rowBase + lrow0;
            bool v = r < M;
            const __half* pa = A + ((size_t)(v ? r : 0) * KT + kb + lc0 * 8);
            cp_async16(sbase + so0, pa, v ? 16 : 0);
            const __half* pb = B + ((size_t)(n0 + lrow0) * KT + kb + lc0 * 8);
            cp_async16(sbase + ARR_BYTES + so0, pb, 16);
        }
        {
            int r = rowBase + lrow1;
            bool v = r < M;
            const __half* pa = A + ((size_t)(v ? r : 0) * KT + kb + lc1 * 8);
            cp_async16(sbase + so1, pa, v ? 16 : 0);
            const __half* pb = B + ((size_t)(n0 + lrow1) * KT + kb + lc1 * 8);
            cp_async16(sbase + ARR_BYTES + so1, pb, 16);
        }
        asm volatile("cp.async.commit_group;" ::: "memory");
    };

    int aoffA = (lane & 15) * APAD + (lane >> 4) * 8;
    int aoffB = (lane & 7) * APAD + ((lane >> 3) & 1) * 8;

    const int NCH = KT / KC;
    issue_chunk(0, 0);
    for (int ch = 0; ch < NCH; ch++) {
        int cur = ch & 1;
        if (ch + 1 < NCH) {
            issue_chunk(ch + 1, cur ^ 1);
            asm volatile("cp.async.wait_group 1;" ::: "memory");
        } else {
            asm volatile("cp.async.wait_group 0;" ::: "memory");
        }
        __syncthreads();
        uint32_t aA = sb + cur * STAGE_BYTES;
        uint32_t aB = aA + ARR_BYTES;
#pragma unroll
        for (int s = 0; s < 2; s++) {
            int k0 = s * 16;
            uint32_t ah[4][4], bh[4][2];
#pragma unroll
            for (int mf = 0; mf < 4; mf++) {
                uint32_t off = ((wm + mf * 16) * APAD + k0 + aoffA) * 2;
                ldsm_x4(ah[mf], aA + off);
            }
#pragma unroll
            for (int nf = 0; nf < 4; nf++) {
                uint32_t off = ((wn + nf * 8) * APAD + k0 + aoffB) * 2;
                ldsm_x2(bh[nf], aB + off);
            }
#pragma unroll
            for (int mf = 0; mf < 4; mf++)
#pragma unroll
                for (int nf = 0; nf < 4; nf++)
                    mma_f16(acc[mf][nf], ah[mf], bh[nf]);
        }
        __syncthreads();
    }

    int lane4 = lane >> 2, lanec = (lane & 3) * 2;
#pragma unroll
    for (int mf = 0; mf < 4; mf++) {
#pragma unroll
        for (int half = 0; half < 2; half++) {
            int row = rowBase + wm + mf * 16 + lane4 + half * 8;
            if (row >= M) continue;
            int l = 0;
            if (EPI == 1) l = winrow_to_l(row);
#pragma unroll
            for (int nf = 0; nf < 4; nf++) {
#pragma unroll
                for (int e = 0; e < 2; e++) {
                    int col = n0 + wn + nf * 8 + lanec + e;
                    float v = acc[mf][nf][half * 2 + e] + bias[col];
                    if (EPI == 0) {
                        g_kv[(size_t)row * 768 + col] = v;
                    } else if (EPI == 1) {
                        size_t idx = (size_t)l * CH + col;
                        g_x[idx] = e1[idx] + e2[idx] + v;
                    } else if (EPI == 2) {
                        float t = tanhf(0.7978845608028654f * (v + 0.044715f * v * v * v));
                        float gv = 0.5f * v * (1.0f + t);
                        g_h1[(size_t)row * 1536 + col] = __float2half_rn(gv);
                    } else {
                        size_t idx = (size_t)row * CH + col;
                        out[idx] = g_x[idx] + v;
                    }
                }
            }
        }
    }
}

// --- fused window attention: R=2, fp16 HFMA2 QK, f16x2 exp2, LDS.64 PV -----
#define ATHREADS 512
#define NWARP 16
#define JPAD 352                 // padded j extent
#define NJP (JPAD / 2)           // 176 j-pairs
// floats: bias 2198 ; half2: k2 16*345, vh2 176*32, pw 16*352
#define ATTN_SMEM (2198 * 4 + 16 * KPAD * 4 + NJP * 32 * 4 + NWARP * JPAD * 4)

__global__ void __launch_bounds__(ATHREADS, 2) attn_kernel(const float* __restrict__ rpb) {
    int win = blockIdx.x, head = blockIdx.y;
    extern __shared__ float sm[];
    float* bias_s = sm;                                // [2197] (log2 domain)
    __half2* k2_s = (__half2*)(bias_s + 2198);         // [16][KPAD] d-pairs
    __half2* vh2_s = k2_s + 16 * KPAD;                 // [176][32] j-pairs
    __half2* pall = vh2_s + NJP * 32;                  // NWARP x JPAD
    int tid = threadIdx.x;
    const size_t base = (size_t)win * NTOK;
    const float LOG2E = 1.4426950408889634f;
    // k2 loader: k2_s[dp][j] = (k[2dp][j], k[2dp+1][j])
    for (int idx = tid; idx < NTOK * 16; idx += ATHREADS) {
        int j = idx >> 4, dp = idx & 15;
        const float2* kv2 = (const float2*)(g_kv + (base + j) * 768 + head * HD);
        float2 kk = kv2[dp];
        k2_s[dp * KPAD + j] = __floats2half2_rn(kk.x, kk.y);
    }
    // vh2 loader: vh2_s[jp][d] = (v[2jp][d], v[2jp+1][d]), zero pad
    for (int idx = tid; idx < NJP * HD; idx += ATHREADS) {
        int jp = idx >> 5, d = idx & 31;
        int j0 = 2 * jp, j1 = 2 * jp + 1;
        float v0 = (j0 < NTOK) ? g_kv[(base + j0) * 768 + 384 + head * HD + d] : 0.f;
        float v1 = (j1 < NTOK) ? g_kv[(base + j1) * 768 + 384 + head * HD + d] : 0.f;
        vh2_s[idx] = __floats2half2_rn(v0, v1);
    }
    for (int idx = tid; idx < 2197; idx += ATHREADS)
        bias_s[idx] = rpb[idx * NHEAD + head] * LOG2E;
    __syncthreads();

    int lane = tid & 31, wid = tid >> 5;
    __half2* pw = pall + wid * JPAD;
    const uint2* pw64 = (const uint2*)pw;
    if (lane < JPAD - NTOK) pw[NTOK + lane] = __float2half2_rn(0.f);

    for (int rp = wid; rp < 172; rp += NWARP) {
        int r0 = rp * 2, r1 = rp * 2 + 1;
        bool has1 = r1 < NTOK;
        int r1c = has1 ? r1 : r0;
        // q rows packed as half2 (r0, r1) per d
        const __half* q0p = g_lnq + (base + r0) * CH + head * HD;
        const __half* q1p = g_lnq + (base + r1c) * CH + head * HD;
        __half2 q2[32];
#pragma unroll
        for (int d = 0; d < 32; d++)
            q2[d] = __halves2half2(q0p[d], q1p[d]);
        int pd0 = r0 / 49, ph0 = (r0 / 7) % 7, pw0 = r0 % 7;
        int pd1 = r1c / 49, ph1 = (r1c / 7) % 7, pw1 = r1c % 7;
        int boff0 = pd0 * 169 + ph0 * 13 + pw0;
        int boff1 = pd1 * 169 + ph1 * 13 + pw1;
        __half2 sv[11];
        __half2 m01 = __float2half2_rn(-60000.f);
#pragma unroll
        for (int t = 0; t < 11; t++) {
            int j = lane + t * 32;
            if (j < NTOK) {
                int kd = j / 49, kh = (j / 7) % 7, kw = j % 7;
                int bo = (6 - kd) * 169 + (6 - kh) * 13 + (6 - kw);
                __half2 s01 = __floats2half2_rn(bias_s[boff0 + bo], bias_s[boff1 + bo]);
#pragma unroll
                for (int dp = 0; dp < 16; dp++) {
                    __half2 kk = k2_s[dp * KPAD + j];
                    s01 = __hfma2(q2[2 * dp], __low2half2(kk), s01);
                    s01 = __hfma2(q2[2 * dp + 1], __high2half2(kk), s01);
                }
                sv[t] = s01;
                m01 = __hmax2(m01, s01);
            } else {
                sv[t] = __float2half2_rn(-60000.f);
            }
        }
#pragma unroll
        for (int o = 16; o > 0; o >>= 1) {
            uint32_t mu = __shfl_xor_sync(0xffffffffu, *(uint32_t*)&m01, o);
            m01 = __hmax2(m01, *(__half2*)&mu);
        }
        float sum0 = 0.f, sum1 = 0.f;
#pragma unroll
        for (int t = 0; t < 11; t++) {
            int j = lane + t * 32;
            if (j < NTOK) {
                __half2 hp = h2exp2(__hsub2(sv[t], m01));
                pw[j] = hp;
                float2 f = __half22float2(hp);
                sum0 += f.x; sum1 += f.y;
            }
        }
#pragma unroll
        for (int o = 16; o > 0; o >>= 1) {
            sum0 += __shfl_xor_sync(0xffffffffu, sum0, o);
            sum1 += __shfl_xor_sync(0xffffffffu, sum1, o);
        }
        float inv0 = 1.0f / sum0, inv1 = 1.0f / sum1;
        __syncwarp();
        // PV: per j-pair, 1 LDS.64 broadcast for both prob words + 1 v-LDS
        float a0 = 0.f, a1 = 0.f;
        for (int c = 0; c < NJP / 8; c++) {
            __half2 acc = __float2half2_rn(0.f);
#pragma unroll
            for (int u = 0; u < 8; u++) {
                int jp = c * 8 + u;
                uint2 pp = pw64[jp];
                __half2 vv = vh2_s[jp * 32 + lane];
                acc = __hfma2(*(__half2*)&pp.x, __low2half2(vv), acc);
                acc = __hfma2(*(__half2*)&pp.y, __high2half2(vv), acc);
            }
            float2 f = __half22float2(acc);
            a0 += f.x; a1 += f.y;
        }
        g_o[(base + r0) * CH + head * HD + lane] = __float2half_rn(a0 * inv0);
        if (has1)
            g_o[(base + r1) * CH + head * HD + lane] = __float2half_rn(a1 * inv1);
        __syncwarp();
    }
}

// ---------------- launch ----------------
extern "C" void kernel_launch(void* const* d_in, const int* in_sizes, int n_in,
                              void* d_out, int out_size) {
    const float* skip = (const float*)d_in[0];
    const float* xup  = (const float*)d_in[1];
    const float* ln1g = (const float*)d_in[5];
    const float* ln1b = (const float*)d_in[6];
    const float* kvw  = (const float*)d_in[7];
    const float* kvb  = (const float*)d_in[8];
    const float* rpb  = (const float*)d_in[9];
    const float* pw   = (const float*)d_in[10];
    const float* pb   = (const float*)d_in[11];
    const float* ln2g = (const float*)d_in[12];
    const float* ln2b = (const float*)d_in[13];
    const float* w1   = (const float*)d_in[14];
    const float* b1   = (const float*)d_in[15];
    const float* w2   = (const float*)d_in[16];
    const float* b2   = (const float*)d_in[17];
    float* out = (float*)d_out;

    cudaFuncSetAttribute(attn_kernel, cudaFuncAttributeMaxDynamicSharedMemorySize, ATTN_SMEM);
    cudaFuncSetAttribute(mma_gemm<0, 384>, cudaFuncAttributeMaxDynamicSharedMemorySize, GEMM_SMEM);
    cudaFuncSetAttribute(mma_gemm<1, 384>, cudaFuncAttributeMaxDynamicSharedMemorySize, GEMM_SMEM);
    cudaFuncSetAttribute(mma_gemm<2, 384>, cudaFuncAttributeMaxDynamicSharedMemorySize, GEMM_SMEM);
    cudaFuncSetAttribute(mma_gemm<3, 1536>, cudaFuncAttributeMaxDynamicSharedMemorySize, GEMM_SMEM);

    wconv<0><<<dim3(768 / 32, 384 / 32), dim3(32, 8)>>>(kvw, 384, 768);
    wconv<1><<<dim3(384 / 32, 384 / 32), dim3(32, 8)>>>(pw, 384, 384);
    wconv<2><<<dim3(1536 / 32, 384 / 32), dim3(32, 8)>>>(w1, 384, 1536);
    wconv<3><<<dim3(384 / 32, 1536 / 32), dim3(32, 8)>>>(w2, 1536, 384);

    ln1_kernel<<<LTOT, 128>>>(skip, xup, ln1g, ln1b);
    mma_gemm<0, 384><<<dim3(6, 172), 256, GEMM_SMEM>>>(kvb, nullptr, nullptr, nullptr, LTOT);
    attn_kernel<<<dim3(NWIN, NHEAD), ATHREADS, ATTN_SMEM>>>(rpb);
    mma_gemm<1, 384><<<dim3(3, 172), 256, GEMM_SMEM>>>(pb, skip, xup, nullptr, LTOT);
    ln2_kernel<<<LTOT, 128>>>(ln2g, ln2b);
    mma_gemm<2, 384><<<dim3(12, 172), 256, GEMM_SMEM>>>(b1, nullptr, nullptr, nullptr, LTOT);
    mma_gemm<3, 1536><<<dim3(3, 172), 256, GEMM_SMEM>>>(b2, nullptr, nullptr, out, LTOT);
}